// round 1
// baseline (speedup 1.0000x reference)
#include <cuda_runtime.h>
#include <math.h>

#define NB    20
#define BSZ   64
#define DM    768
#define NH    12
#define DI    3072
#define QKV_N (3*DM)          // 2304
#define S_TOK (2*NB*BSZ)      // 2560 tokens per stream
#define S2    (2*S_TOK)       // 5120 both streams

// ---------------- scratch (device globals; no allocation allowed) ----------
__device__ float g_a   [S2 * DM];      // LN outputs (both streams contiguous)
__device__ float g_qkv [S2 * QKV_N];   // qkv (stream0 then stream1)
__device__ float g_attm[S2 * DM];      // merged attention output
__device__ float g_xa  [S2 * DM];      // x + attn proj (residual 1)
__device__ float g_h   [S2 * DI];      // MLP hidden
__device__ float g_ph  [S_TOK * 2*DM]; // pose head hidden (2560 x 1536)

// ---------------- LayerNorm: one block per row, 256 threads ----------------
__global__ void ln_kernel(const float* __restrict__ x, const float* __restrict__ g,
                          const float* __restrict__ b, float* __restrict__ out) {
    int row = blockIdx.x;
    const float* xr = x + (size_t)row * DM;
    float* orow = out + (size_t)row * DM;
    int t = threadIdx.x;
    float v0 = xr[t], v1 = xr[t + 256], v2 = xr[t + 512];
    float s = v0 + v1 + v2;
    float ss = v0*v0 + v1*v1 + v2*v2;
    #pragma unroll
    for (int o = 16; o; o >>= 1) {
        s  += __shfl_xor_sync(0xffffffffu, s,  o);
        ss += __shfl_xor_sync(0xffffffffu, ss, o);
    }
    __shared__ float rs[8], rss[8];
    __shared__ float mean_s, rstd_s;
    int w = t >> 5;
    if ((t & 31) == 0) { rs[w] = s; rss[w] = ss; }
    __syncthreads();
    if (t == 0) {
        float S = 0.f, SS = 0.f;
        #pragma unroll
        for (int i = 0; i < 8; i++) { S += rs[i]; SS += rss[i]; }
        float m = S * (1.0f / 768.0f);
        float var = SS * (1.0f / 768.0f) - m * m;
        mean_s = m;
        rstd_s = rsqrtf(var + 1e-5f);
    }
    __syncthreads();
    float m = mean_s, r = rstd_s;
    orow[t]       = (v0 - m) * r * g[t]       + b[t];
    orow[t + 256] = (v1 - m) * r * g[t + 256] + b[t + 256];
    orow[t + 512] = (v2 - m) * r * g[t + 512] + b[t + 512];
}

// ---------------- Generic fp32 GEMM: C = act(A@B + bias) [+ resid] ---------
// A [M,K] row-major, B [K,N] row-major. BM=BN=64, BK=16, 256 thr, 4x4 micro.
// M%64==0, N%64==0, K%16==0 hold for all call sites.
#define BM 64
#define BN 64
#define BK 16
__global__ void gemm_kernel(const float* __restrict__ A, const float* __restrict__ B,
                            const float* __restrict__ bias, const float* __restrict__ resid,
                            float* __restrict__ C, int M, int N, int K, int act) {
    __shared__ float As[BK][BM + 1];
    __shared__ float Bs[BK][BN];
    int t = threadIdx.x;
    int tx = t & 15, ty = t >> 4;
    int n0 = blockIdx.x * BN, m0 = blockIdx.y * BM;
    float acc[4][4] = {};
    for (int k0 = 0; k0 < K; k0 += BK) {
        #pragma unroll
        for (int i = t; i < BM * BK; i += 256) {
            int m = i >> 4, k = i & 15;
            As[k][m] = A[(size_t)(m0 + m) * K + k0 + k];
        }
        #pragma unroll
        for (int i = t; i < BK * BN; i += 256) {
            int k = i >> 6, n = i & 63;
            Bs[k][n] = B[(size_t)(k0 + k) * N + n0 + n];
        }
        __syncthreads();
        #pragma unroll
        for (int kk = 0; kk < BK; kk++) {
            float af[4], bf[4];
            #pragma unroll
            for (int i = 0; i < 4; i++) af[i] = As[kk][ty * 4 + i];
            #pragma unroll
            for (int j = 0; j < 4; j++) bf[j] = Bs[kk][tx * 4 + j];
            #pragma unroll
            for (int i = 0; i < 4; i++)
                #pragma unroll
                for (int j = 0; j < 4; j++)
                    acc[i][j] += af[i] * bf[j];
        }
        __syncthreads();
    }
    #pragma unroll
    for (int i = 0; i < 4; i++) {
        int m = m0 + ty * 4 + i;
        #pragma unroll
        for (int j = 0; j < 4; j++) {
            int n = n0 + tx * 4 + j;
            float v = acc[i][j] + bias[n];
            if (act == 1) v = 0.5f * v * (1.0f + erff(v * 0.70710678118654752440f));
            if (resid) v += resid[(size_t)m * N + n];
            C[(size_t)m * N + n] = v;
        }
    }
}

// ---------------- Multiend block attention (flash-style) -------------------
// One CTA per (stream e, batch b, head h, query-block i). 256 threads.
// Past key/value blocks always come from STREAM 0's qkv (k0, v0);
// the diagonal (unmasked) block uses the stream's own qkv.
__global__ void attn_kernel(const float* __restrict__ qkv0, const float* __restrict__ qkv1,
                            float* __restrict__ attm0, float* __restrict__ attm1) {
    extern __shared__ float sm[];
    float* q_s  = sm;                 // 64 x 65
    float* kv_s = sm + 64 * 65;       // 64 x 65
    float* s_s  = sm + 2 * 64 * 65;   // 64 x 65
    float* m_s  = sm + 3 * 64 * 65;   // 64
    float* l_s  = m_s + 64;           // 64
    float* al_s = l_s + 64;           // 64

    const int i = blockIdx.x, h = blockIdx.y;
    const int e = blockIdx.z >> 1, b = blockIdx.z & 1;
    const float* qkvE = e ? qkv1 : qkv0;
    float* attm = e ? attm1 : attm0;
    const int t = threadIdx.x, tx = t & 15, ty = t >> 4;
    const int qrow0 = (b * NB + i) * BSZ;
    const float scale = 0.125f;   // 1/sqrt(64)

    // load Q tile (columns [768, 832) + h*64 of qkv)
    for (int idx = t; idx < 64 * 64; idx += 256) {
        int qi = idx >> 6, d = idx & 63;
        q_s[qi * 65 + d] = qkvE[(size_t)(qrow0 + qi) * QKV_N + DM + h * 64 + d];
    }
    if (t < 64) { m_s[t] = -1e30f; l_s[t] = 0.f; }
    float acc[4][4] = {};

    for (int j = 0; j <= i; ++j) {
        const float* kvb = (j < i) ? qkv0 : qkvE;   // past from stream 0, diag from own
        const int krow0 = (b * NB + j) * BSZ;
        __syncthreads();   // protect kv_s/s_s from previous iteration's readers
        // K tile
        for (int idx = t; idx < 4096; idx += 256) {
            int kj = idx >> 6, d = idx & 63;
            kv_s[kj * 65 + d] = kvb[(size_t)(krow0 + kj) * QKV_N + 2 * DM + h * 64 + d];
        }
        __syncthreads();
        // S = scale * Q K^T  (4x4 microtile per thread)
        {
            float sv[4][4] = {};
            for (int d = 0; d < 64; d++) {
                float qa[4], ka[4];
                #pragma unroll
                for (int ii = 0; ii < 4; ii++) qa[ii] = q_s[(ty * 4 + ii) * 65 + d];
                #pragma unroll
                for (int jj = 0; jj < 4; jj++) ka[jj] = kv_s[(tx * 4 + jj) * 65 + d];
                #pragma unroll
                for (int ii = 0; ii < 4; ii++)
                    #pragma unroll
                    for (int jj = 0; jj < 4; jj++)
                        sv[ii][jj] += qa[ii] * ka[jj];
            }
            #pragma unroll
            for (int ii = 0; ii < 4; ii++)
                #pragma unroll
                for (int jj = 0; jj < 4; jj++)
                    s_s[(ty * 4 + ii) * 65 + tx * 4 + jj] = sv[ii][jj] * scale;
        }
        __syncthreads();
        // online softmax: 4 lanes per query row
        {
            int q = t >> 2, p = t & 3;
            int base = q * 65 + p * 16;
            float lm = -1e30f;
            #pragma unroll
            for (int kk = 0; kk < 16; kk++) lm = fmaxf(lm, s_s[base + kk]);
            lm = fmaxf(lm, __shfl_xor_sync(0xffffffffu, lm, 1));
            lm = fmaxf(lm, __shfl_xor_sync(0xffffffffu, lm, 2));
            float mold = m_s[q];
            float mnew = fmaxf(mold, lm);
            float ls = 0.f;
            #pragma unroll
            for (int kk = 0; kk < 16; kk++) {
                float pp = __expf(s_s[base + kk] - mnew);
                s_s[base + kk] = pp;
                ls += pp;
            }
            ls += __shfl_xor_sync(0xffffffffu, ls, 1);
            ls += __shfl_xor_sync(0xffffffffu, ls, 2);
            if (p == 0) {
                float alpha = __expf(mold - mnew);
                al_s[q] = alpha;
                l_s[q] = l_s[q] * alpha + ls;
                m_s[q] = mnew;
            }
        }
        // V tile (overwrites kv_s; its last readers synced above)
        for (int idx = t; idx < 4096; idx += 256) {
            int kj = idx >> 6, d = idx & 63;
            kv_s[kj * 65 + d] = kvb[(size_t)(krow0 + kj) * QKV_N + h * 64 + d];
        }
        __syncthreads();
        // rescale + accumulate O += P V
        {
            float alr[4];
            #pragma unroll
            for (int ii = 0; ii < 4; ii++) alr[ii] = al_s[ty * 4 + ii];
            #pragma unroll
            for (int ii = 0; ii < 4; ii++)
                #pragma unroll
                for (int jj = 0; jj < 4; jj++)
                    acc[ii][jj] *= alr[ii];
            for (int kk = 0; kk < 64; kk++) {
                float pv[4], vv[4];
                #pragma unroll
                for (int ii = 0; ii < 4; ii++) pv[ii] = s_s[(ty * 4 + ii) * 65 + kk];
                #pragma unroll
                for (int jj = 0; jj < 4; jj++) vv[jj] = kv_s[kk * 65 + tx * 4 + jj];
                #pragma unroll
                for (int ii = 0; ii < 4; ii++)
                    #pragma unroll
                    for (int jj = 0; jj < 4; jj++)
                        acc[ii][jj] += pv[ii] * vv[jj];
            }
        }
    }
    // epilogue: divide by l, write merged-head layout
    #pragma unroll
    for (int ii = 0; ii < 4; ii++) {
        float inv = 1.0f / l_s[ty * 4 + ii];
        #pragma unroll
        for (int jj = 0; jj < 4; jj++) {
            attm[(size_t)(qrow0 + ty * 4 + ii) * DM + h * 64 + tx * 4 + jj] = acc[ii][jj] * inv;
        }
    }
}

// ---------------- Pose projection + quaternion normalize -------------------
// one block (256 thr) per row; 7 outputs via per-thread partials + reduction
__global__ void pose_kernel(const float* __restrict__ ph, const float* __restrict__ w,
                            const float* __restrict__ bias, float* __restrict__ out) {
    int row = blockIdx.x;
    int t = threadIdx.x;
    const float* hr = ph + (size_t)row * (2 * DM);
    float part[7] = {};
    for (int j = t; j < 2 * DM; j += 256) {
        float hv = hr[j];
        #pragma unroll
        for (int o = 0; o < 7; o++) part[o] += hv * w[j * 7 + o];
    }
    #pragma unroll
    for (int o = 0; o < 7; o++)
        #pragma unroll
        for (int s = 16; s; s >>= 1)
            part[o] += __shfl_xor_sync(0xffffffffu, part[o], s);
    __shared__ float red[8][7];
    int wi = t >> 5;
    if ((t & 31) == 0)
        #pragma unroll
        for (int o = 0; o < 7; o++) red[wi][o] = part[o];
    __syncthreads();
    if (t == 0) {
        float hv[7];
        #pragma unroll
        for (int o = 0; o < 7; o++) {
            hv[o] = bias[o];
            for (int k = 0; k < 8; k++) hv[o] += red[k][o];
        }
        float q0 = hv[3], q1 = hv[4], q2 = hv[5], q3 = hv[6];
        float inv = rsqrtf(q0*q0 + q1*q1 + q2*q2 + q3*q3);
        q0 *= inv; q1 *= inv; q2 *= inv; q3 *= inv;
        if (q0 < 0.f) { q0 = -q0; q1 = -q1; q2 = -q2; q3 = -q3; }
        float* orow = out + (size_t)row * 7;
        orow[0] = hv[0]; orow[1] = hv[1]; orow[2] = hv[2];
        orow[3] = q0; orow[4] = q1; orow[5] = q2; orow[6] = q3;
    }
}

// ---------------------------------------------------------------------------
extern "C" void kernel_launch(void* const* d_in, const int* in_sizes, int n_in,
                              void* d_out, int out_size) {
    const float* x0        = (const float*)d_in[0];
    const float* x1        = (const float*)d_in[1];
    const float* ln1_g     = (const float*)d_in[2];
    const float* ln1_b     = (const float*)d_in[3];
    const float* attn_w    = (const float*)d_in[4];
    const float* attn_b    = (const float*)d_in[5];
    const float* proj_w    = (const float*)d_in[6];
    const float* proj_b    = (const float*)d_in[7];
    const float* ln2_g     = (const float*)d_in[8];
    const float* ln2_b     = (const float*)d_in[9];
    const float* fc_w      = (const float*)d_in[10];
    const float* fc_b      = (const float*)d_in[11];
    const float* mproj_w   = (const float*)d_in[12];
    const float* mproj_b   = (const float*)d_in[13];
    const float* pose_fc_w = (const float*)d_in[14];
    const float* pose_fc_b = (const float*)d_in[15];
    const float* pose_pw   = (const float*)d_in[16];
    const float* pose_pb   = (const float*)d_in[17];
    float* out = (float*)d_out;

    float *a, *qkv, *attmp, *xa, *hbuf, *ph;
    cudaGetSymbolAddress((void**)&a,     g_a);
    cudaGetSymbolAddress((void**)&qkv,   g_qkv);
    cudaGetSymbolAddress((void**)&attmp, g_attm);
    cudaGetSymbolAddress((void**)&xa,    g_xa);
    cudaGetSymbolAddress((void**)&hbuf,  g_h);
    cudaGetSymbolAddress((void**)&ph,    g_ph);

    const size_t OFF = (size_t)S_TOK * DM;          // stream stride in y/x space
    const int attn_smem = (3 * 64 * 65 + 192) * (int)sizeof(float);  // 50688 B
    cudaFuncSetAttribute(attn_kernel, cudaFuncAttributeMaxDynamicSharedMemorySize, attn_smem);

    // LN1 (per-stream inputs are not contiguous)
    ln_kernel<<<S_TOK, 256>>>(x0, ln1_g, ln1_b, a);
    ln_kernel<<<S_TOK, 256>>>(x1, ln1_g, ln1_b, a + OFF);
    // QKV for both streams in one launch (scratch is contiguous)
    gemm_kernel<<<dim3(QKV_N / 64, S2 / 64), 256>>>(a, attn_w, attn_b, nullptr, qkv,
                                                    S2, QKV_N, DM, 0);
    // attention (both streams, all heads/blocks)
    attn_kernel<<<dim3(NB, NH, 4), 256, attn_smem>>>(qkv, qkv + (size_t)S_TOK * QKV_N,
                                                     attmp, attmp + OFF);
    // attn out projection + residual (residual pointers differ per stream)
    gemm_kernel<<<dim3(DM / 64, S_TOK / 64), 256>>>(attmp, proj_w, proj_b, x0, xa,
                                                    S_TOK, DM, DM, 0);
    gemm_kernel<<<dim3(DM / 64, S_TOK / 64), 256>>>(attmp + OFF, proj_w, proj_b, x1, xa + OFF,
                                                    S_TOK, DM, DM, 0);
    // LN2 (contiguous) + MLP
    ln_kernel<<<S2, 256>>>(xa, ln2_g, ln2_b, a);
    gemm_kernel<<<dim3(DI / 64, S2 / 64), 256>>>(a, fc_w, fc_b, nullptr, hbuf,
                                                 S2, DI, DM, 1);
    // mproj + residual -> writes y0 || y1 directly into d_out
    gemm_kernel<<<dim3(DM / 64, S2 / 64), 256>>>(hbuf, mproj_w, mproj_b, xa, out,
                                                 S2, DM, DI, 0);
    // pose head on y1
    gemm_kernel<<<dim3((2 * DM) / 64, S_TOK / 64), 256>>>(out + OFF, pose_fc_w, pose_fc_b,
                                                          nullptr, ph, S_TOK, 2 * DM, DM, 1);
    pose_kernel<<<S_TOK, 256>>>(ph, pose_pw, pose_pb, out + 2 * OFF);
}

// round 6
// speedup vs baseline: 1.1862x; 1.1862x over previous
#include <cuda_runtime.h>
#include <math.h>

#define NB    20
#define BSZ   64
#define DM    768
#define NH    12
#define DI    3072
#define QKV_N (3*DM)          // 2304
#define S_TOK (2*NB*BSZ)      // 2560 tokens per stream
#define S2    (2*S_TOK)       // 5120 both streams

// ---------------- scratch (device globals; no allocation allowed) ----------
__device__ float g_a   [S2 * DM];
__device__ float g_qkv [S2 * QKV_N];
__device__ float g_attm[S2 * DM];
__device__ float g_xa  [S2 * DM];
__device__ float g_h   [S2 * DI];
__device__ float g_ph  [S_TOK * 2*DM];

// ---------------- LayerNorm ------------------------------------------------
__global__ void ln_kernel(const float* __restrict__ x, const float* __restrict__ g,
                          const float* __restrict__ b, float* __restrict__ out) {
    int row = blockIdx.x;
    const float* xr = x + (size_t)row * DM;
    float* orow = out + (size_t)row * DM;
    int t = threadIdx.x;
    float v0 = xr[t], v1 = xr[t + 256], v2 = xr[t + 512];
    float s = v0 + v1 + v2;
    float ss = v0*v0 + v1*v1 + v2*v2;
    #pragma unroll
    for (int o = 16; o; o >>= 1) {
        s  += __shfl_xor_sync(0xffffffffu, s,  o);
        ss += __shfl_xor_sync(0xffffffffu, ss, o);
    }
    __shared__ float rs[8], rss[8];
    __shared__ float mean_s, rstd_s;
    int w = t >> 5;
    if ((t & 31) == 0) { rs[w] = s; rss[w] = ss; }
    __syncthreads();
    if (t == 0) {
        float S = 0.f, SS = 0.f;
        #pragma unroll
        for (int i = 0; i < 8; i++) { S += rs[i]; SS += rss[i]; }
        float m = S * (1.0f / 768.0f);
        float var = SS * (1.0f / 768.0f) - m * m;
        mean_s = m;
        rstd_s = rsqrtf(var + 1e-5f);
    }
    __syncthreads();
    float m = mean_s, r = rstd_s;
    orow[t]       = (v0 - m) * r * g[t]       + b[t];
    orow[t + 256] = (v1 - m) * r * g[t + 256] + b[t + 256];
    orow[t + 512] = (v2 - m) * r * g[t + 512] + b[t + 512];
}

// ---------------- 3xTF32 tensor-core GEMM (fp32-accurate) ------------------
// C[M,N] = act(A[M,K] @ B[K,N] + bias) [+ resid]
// BM=128, BN=64, BK=16, 256 threads = 8 warps (4x2), warp tile 32x32.
// Each operand split x = x_hi + x_lo (tf32 each); C += lo*hi + hi*lo + hi*hi.
// Shared memory is DYNAMIC (59392 B > 48 KB static limit).
#define TBM 128
#define TBN 64
#define TBK 16
#define ASTRIDE 20
#define BSTRIDE 72
#define ASZ (TBM * ASTRIDE)          // 2560 floats per (buf,part)
#define BSZT (TBK * BSTRIDE)         // 1152 floats per (buf,part)
#define GEMM_SMEM_BYTES ((2 * 2 * ASZ + 2 * 2 * BSZT) * 4)   // 59392

__device__ __forceinline__ unsigned f2tf32(float f) {
    unsigned u;
    asm("cvt.rna.tf32.f32 %0, %1;" : "=r"(u) : "f"(f));
    return u;
}
__device__ __forceinline__ void tf32split(float x, float& hi, float& lo) {
    unsigned h = f2tf32(x);
    hi = __uint_as_float(h);
    lo = __uint_as_float(f2tf32(x - hi));
}

#define MMA_TF32(C, Ar, Br) \
    asm volatile( \
        "mma.sync.aligned.m16n8k8.row.col.f32.tf32.tf32.f32 " \
        "{%0,%1,%2,%3}, {%4,%5,%6,%7}, {%8,%9}, {%0,%1,%2,%3};" \
        : "+f"(C[0]), "+f"(C[1]), "+f"(C[2]), "+f"(C[3]) \
        : "r"(Ar[0]), "r"(Ar[1]), "r"(Ar[2]), "r"(Ar[3]), \
          "r"(Br[0]), "r"(Br[1]))

__global__ void __launch_bounds__(256)
gemm_tf32_kernel(const float* __restrict__ A, const float* __restrict__ B,
                 const float* __restrict__ bias, const float* __restrict__ resid,
                 float* __restrict__ C, int M, int N, int K, int act) {
    extern __shared__ float smem_dyn[];
    // layout: As[buf][part] then Bs[buf][part]
    float* Asp[2][2];
    float* Bsp[2][2];
    #pragma unroll
    for (int bu = 0; bu < 2; bu++)
        #pragma unroll
        for (int p = 0; p < 2; p++) {
            Asp[bu][p] = smem_dyn + (bu * 2 + p) * ASZ;
            Bsp[bu][p] = smem_dyn + 4 * ASZ + (bu * 2 + p) * BSZT;
        }

    const int t = threadIdx.x;
    const int warp = t >> 5, lane = t & 31;
    const int g = lane >> 2, tig = lane & 3;
    const int wm = warp >> 1, wn = warp & 1;
    const int m0 = blockIdx.y * TBM, n0 = blockIdx.x * TBN;

    const int am0 = t >> 2,         akq0 = t & 3;
    const int am1 = (t + 256) >> 2, akq1 = t & 3;
    const int bk = t >> 4, bnq = t & 15;

    float c[2][4][4];
    #pragma unroll
    for (int i = 0; i < 2; i++)
        #pragma unroll
        for (int j = 0; j < 4; j++)
            #pragma unroll
            for (int r = 0; r < 4; r++) c[i][j][r] = 0.f;

    const int nIter = K / TBK;

    float4 ra0 = *(const float4*)&A[(size_t)(m0 + am0) * K + akq0 * 4];
    float4 ra1 = *(const float4*)&A[(size_t)(m0 + am1) * K + akq1 * 4];
    float4 rb  = *(const float4*)&B[(size_t)bk * N + n0 + bnq * 4];
    {
        const int ab0 = am0 * ASTRIDE + akq0 * 4;
        const int ab1 = am1 * ASTRIDE + akq1 * 4;
        const int bb  = bk * BSTRIDE + bnq * 4;
        float hi, lo;
        const float* pa0 = &ra0.x; const float* pa1 = &ra1.x; const float* pb = &rb.x;
        #pragma unroll
        for (int q = 0; q < 4; q++) {
            tf32split(pa0[q], hi, lo); Asp[0][0][ab0+q] = hi; Asp[0][1][ab0+q] = lo;
            tf32split(pa1[q], hi, lo); Asp[0][0][ab1+q] = hi; Asp[0][1][ab1+q] = lo;
            tf32split(pb[q],  hi, lo); Bsp[0][0][bb+q]  = hi; Bsp[0][1][bb+q]  = lo;
        }
    }
    __syncthreads();

    for (int it = 0; it < nIter; ++it) {
        const int buf = it & 1;
        if (it + 1 < nIter) {
            int k0 = (it + 1) * TBK;
            ra0 = *(const float4*)&A[(size_t)(m0 + am0) * K + k0 + akq0 * 4];
            ra1 = *(const float4*)&A[(size_t)(m0 + am1) * K + k0 + akq1 * 4];
            rb  = *(const float4*)&B[(size_t)(k0 + bk) * N + n0 + bnq * 4];
        }
        const unsigned* ash = (const unsigned*)Asp[buf][0];
        const unsigned* asl = (const unsigned*)Asp[buf][1];
        const unsigned* bsh = (const unsigned*)Bsp[buf][0];
        const unsigned* bsl = (const unsigned*)Bsp[buf][1];
        #pragma unroll
        for (int s = 0; s < 2; s++) {
            const int kb = s * 8;
            unsigned afh[2][4], afl[2][4], bfh[4][2], bfl[4][2];
            #pragma unroll
            for (int i = 0; i < 2; i++) {
                int mr = wm * 32 + i * 16;
                int i0 = (mr + g)     * ASTRIDE + kb + tig;
                int i1 = (mr + g + 8) * ASTRIDE + kb + tig;
                afh[i][0] = ash[i0];     afh[i][1] = ash[i1];
                afh[i][2] = ash[i0 + 4]; afh[i][3] = ash[i1 + 4];
                afl[i][0] = asl[i0];     afl[i][1] = asl[i1];
                afl[i][2] = asl[i0 + 4]; afl[i][3] = asl[i1 + 4];
            }
            #pragma unroll
            for (int j = 0; j < 4; j++) {
                int nb = wn * 32 + j * 8;
                int j0 = (kb + tig)     * BSTRIDE + nb + g;
                int j1 = (kb + tig + 4) * BSTRIDE + nb + g;
                bfh[j][0] = bsh[j0]; bfh[j][1] = bsh[j1];
                bfl[j][0] = bsl[j0]; bfl[j][1] = bsl[j1];
            }
            #pragma unroll
            for (int i = 0; i < 2; i++)
                #pragma unroll
                for (int j = 0; j < 4; j++) {
                    MMA_TF32(c[i][j], afl[i], bfh[j]);   // lo*hi
                    MMA_TF32(c[i][j], afh[i], bfl[j]);   // hi*lo
                    MMA_TF32(c[i][j], afh[i], bfh[j]);   // hi*hi
                }
        }
        if (it + 1 < nIter) {
            const int nb2 = buf ^ 1;
            const int ab0 = am0 * ASTRIDE + akq0 * 4;
            const int ab1 = am1 * ASTRIDE + akq1 * 4;
            const int bb  = bk * BSTRIDE + bnq * 4;
            float hi, lo;
            const float* pa0 = &ra0.x; const float* pa1 = &ra1.x; const float* pb = &rb.x;
            #pragma unroll
            for (int q = 0; q < 4; q++) {
                tf32split(pa0[q], hi, lo); Asp[nb2][0][ab0+q] = hi; Asp[nb2][1][ab0+q] = lo;
                tf32split(pa1[q], hi, lo); Asp[nb2][0][ab1+q] = hi; Asp[nb2][1][ab1+q] = lo;
                tf32split(pb[q],  hi, lo); Bsp[nb2][0][bb+q]  = hi; Bsp[nb2][1][bb+q]  = lo;
            }
        }
        __syncthreads();
    }

    #pragma unroll
    for (int i = 0; i < 2; i++) {
        int r0 = m0 + wm * 32 + i * 16 + g;
        #pragma unroll
        for (int j = 0; j < 4; j++) {
            int col = n0 + wn * 32 + j * 8 + tig * 2;
            float b0 = bias[col], b1 = bias[col + 1];
            #pragma unroll
            for (int half = 0; half < 2; half++) {
                int row = r0 + half * 8;
                float v0 = c[i][j][half * 2 + 0] + b0;
                float v1 = c[i][j][half * 2 + 1] + b1;
                if (act == 1) {
                    v0 = 0.5f * v0 * (1.0f + erff(v0 * 0.70710678118654752440f));
                    v1 = 0.5f * v1 * (1.0f + erff(v1 * 0.70710678118654752440f));
                }
                if (resid) {
                    const float2 rr = *(const float2*)&resid[(size_t)row * N + col];
                    v0 += rr.x; v1 += rr.y;
                }
                float2 o; o.x = v0; o.y = v1;
                *(float2*)&C[(size_t)row * N + col] = o;
            }
        }
    }
}

// ---------------- Multiend block attention (flash-style, fp32 exact) -------
__global__ void attn_kernel(const float* __restrict__ qkv0, const float* __restrict__ qkv1,
                            float* __restrict__ attm0, float* __restrict__ attm1) {
    extern __shared__ float sm[];
    float* q_s  = sm;
    float* kv_s = sm + 64 * 65;
    float* s_s  = sm + 2 * 64 * 65;
    float* m_s  = sm + 3 * 64 * 65;
    float* l_s  = m_s + 64;
    float* al_s = l_s + 64;

    const int i = blockIdx.x, h = blockIdx.y;
    const int e = blockIdx.z >> 1, b = blockIdx.z & 1;
    const float* qkvE = e ? qkv1 : qkv0;
    float* attm = e ? attm1 : attm0;
    const int t = threadIdx.x, tx = t & 15, ty = t >> 4;
    const int qrow0 = (b * NB + i) * BSZ;
    const float scale = 0.125f;

    for (int idx = t; idx < 64 * 64; idx += 256) {
        int qi = idx >> 6, d = idx & 63;
        q_s[qi * 65 + d] = qkvE[(size_t)(qrow0 + qi) * QKV_N + DM + h * 64 + d];
    }
    if (t < 64) { m_s[t] = -1e30f; l_s[t] = 0.f; }
    float acc[4][4] = {};

    for (int j = 0; j <= i; ++j) {
        const float* kvb = (j < i) ? qkv0 : qkvE;
        const int krow0 = (b * NB + j) * BSZ;
        __syncthreads();
        for (int idx = t; idx < 4096; idx += 256) {
            int kj = idx >> 6, d = idx & 63;
            kv_s[kj * 65 + d] = kvb[(size_t)(krow0 + kj) * QKV_N + 2 * DM + h * 64 + d];
        }
        __syncthreads();
        {
            float sv[4][4] = {};
            for (int d = 0; d < 64; d++) {
                float qa[4], ka[4];
                #pragma unroll
                for (int ii = 0; ii < 4; ii++) qa[ii] = q_s[(ty * 4 + ii) * 65 + d];
                #pragma unroll
                for (int jj = 0; jj < 4; jj++) ka[jj] = kv_s[(tx * 4 + jj) * 65 + d];
                #pragma unroll
                for (int ii = 0; ii < 4; ii++)
                    #pragma unroll
                    for (int jj = 0; jj < 4; jj++)
                        sv[ii][jj] += qa[ii] * ka[jj];
            }
            #pragma unroll
            for (int ii = 0; ii < 4; ii++)
                #pragma unroll
                for (int jj = 0; jj < 4; jj++)
                    s_s[(ty * 4 + ii) * 65 + tx * 4 + jj] = sv[ii][jj] * scale;
        }
        __syncthreads();
        {
            int q = t >> 2, p = t & 3;
            int base = q * 65 + p * 16;
            float lm = -1e30f;
            #pragma unroll
            for (int kk = 0; kk < 16; kk++) lm = fmaxf(lm, s_s[base + kk]);
            lm = fmaxf(lm, __shfl_xor_sync(0xffffffffu, lm, 1));
            lm = fmaxf(lm, __shfl_xor_sync(0xffffffffu, lm, 2));
            float mold = m_s[q];
            float mnew = fmaxf(mold, lm);
            float ls = 0.f;
            #pragma unroll
            for (int kk = 0; kk < 16; kk++) {
                float pp = __expf(s_s[base + kk] - mnew);
                s_s[base + kk] = pp;
                ls += pp;
            }
            ls += __shfl_xor_sync(0xffffffffu, ls, 1);
            ls += __shfl_xor_sync(0xffffffffu, ls, 2);
            if (p == 0) {
                float alpha = __expf(mold - mnew);
                al_s[q] = alpha;
                l_s[q] = l_s[q] * alpha + ls;
                m_s[q] = mnew;
            }
        }
        for (int idx = t; idx < 4096; idx += 256) {
            int kj = idx >> 6, d = idx & 63;
            kv_s[kj * 65 + d] = kvb[(size_t)(krow0 + kj) * QKV_N + h * 64 + d];
        }
        __syncthreads();
        {
            float alr[4];
            #pragma unroll
            for (int ii = 0; ii < 4; ii++) alr[ii] = al_s[ty * 4 + ii];
            #pragma unroll
            for (int ii = 0; ii < 4; ii++)
                #pragma unroll
                for (int jj = 0; jj < 4; jj++)
                    acc[ii][jj] *= alr[ii];
            for (int kk = 0; kk < 64; kk++) {
                float pv[4], vv[4];
                #pragma unroll
                for (int ii = 0; ii < 4; ii++) pv[ii] = s_s[(ty * 4 + ii) * 65 + kk];
                #pragma unroll
                for (int jj = 0; jj < 4; jj++) vv[jj] = kv_s[kk * 65 + tx * 4 + jj];
                #pragma unroll
                for (int ii = 0; ii < 4; ii++)
                    #pragma unroll
                    for (int jj = 0; jj < 4; jj++)
                        acc[ii][jj] += pv[ii] * vv[jj];
            }
        }
    }
    #pragma unroll
    for (int ii = 0; ii < 4; ii++) {
        float inv = 1.0f / l_s[ty * 4 + ii];
        #pragma unroll
        for (int jj = 0; jj < 4; jj++) {
            attm[(size_t)(qrow0 + ty * 4 + ii) * DM + h * 64 + tx * 4 + jj] = acc[ii][jj] * inv;
        }
    }
}

// ---------------- Pose projection + quaternion normalize -------------------
__global__ void pose_kernel(const float* __restrict__ ph, const float* __restrict__ w,
                            const float* __restrict__ bias, float* __restrict__ out) {
    int row = blockIdx.x;
    int t = threadIdx.x;
    const float* hr = ph + (size_t)row * (2 * DM);
    float part[7] = {};
    for (int j = t; j < 2 * DM; j += 256) {
        float hv = hr[j];
        #pragma unroll
        for (int o = 0; o < 7; o++) part[o] += hv * w[j * 7 + o];
    }
    #pragma unroll
    for (int o = 0; o < 7; o++)
        #pragma unroll
        for (int s = 16; s; s >>= 1)
            part[o] += __shfl_xor_sync(0xffffffffu, part[o], s);
    __shared__ float red[8][7];
    int wi = t >> 5;
    if ((t & 31) == 0)
        #pragma unroll
        for (int o = 0; o < 7; o++) red[wi][o] = part[o];
    __syncthreads();
    if (t == 0) {
        float hv[7];
        #pragma unroll
        for (int o = 0; o < 7; o++) {
            hv[o] = bias[o];
            for (int k = 0; k < 8; k++) hv[o] += red[k][o];
        }
        float q0 = hv[3], q1 = hv[4], q2 = hv[5], q3 = hv[6];
        float inv = rsqrtf(q0*q0 + q1*q1 + q2*q2 + q3*q3);
        q0 *= inv; q1 *= inv; q2 *= inv; q3 *= inv;
        if (q0 < 0.f) { q0 = -q0; q1 = -q1; q2 = -q2; q3 = -q3; }
        float* orow = out + (size_t)row * 7;
        orow[0] = hv[0]; orow[1] = hv[1]; orow[2] = hv[2];
        orow[3] = q0; orow[4] = q1; orow[5] = q2; orow[6] = q3;
    }
}

// ---------------------------------------------------------------------------
extern "C" void kernel_launch(void* const* d_in, const int* in_sizes, int n_in,
                              void* d_out, int out_size) {
    const float* x0        = (const float*)d_in[0];
    const float* x1        = (const float*)d_in[1];
    const float* ln1_g     = (const float*)d_in[2];
    const float* ln1_b     = (const float*)d_in[3];
    const float* attn_w    = (const float*)d_in[4];
    const float* attn_b    = (const float*)d_in[5];
    const float* proj_w    = (const float*)d_in[6];
    const float* proj_b    = (const float*)d_in[7];
    const float* ln2_g     = (const float*)d_in[8];
    const float* ln2_b     = (const float*)d_in[9];
    const float* fc_w      = (const float*)d_in[10];
    const float* fc_b      = (const float*)d_in[11];
    const float* mproj_w   = (const float*)d_in[12];
    const float* mproj_b   = (const float*)d_in[13];
    const float* pose_fc_w = (const float*)d_in[14];
    const float* pose_fc_b = (const float*)d_in[15];
    const float* pose_pw   = (const float*)d_in[16];
    const float* pose_pb   = (const float*)d_in[17];
    float* out = (float*)d_out;

    float *a, *qkv, *attmp, *xa, *hbuf, *ph;
    cudaGetSymbolAddress((void**)&a,     g_a);
    cudaGetSymbolAddress((void**)&qkv,   g_qkv);
    cudaGetSymbolAddress((void**)&attmp, g_attm);
    cudaGetSymbolAddress((void**)&xa,    g_xa);
    cudaGetSymbolAddress((void**)&hbuf,  g_h);
    cudaGetSymbolAddress((void**)&ph,    g_ph);

    const size_t OFF = (size_t)S_TOK * DM;
    const int attn_smem = (3 * 64 * 65 + 192) * (int)sizeof(float);
    cudaFuncSetAttribute(attn_kernel, cudaFuncAttributeMaxDynamicSharedMemorySize, attn_smem);
    cudaFuncSetAttribute(gemm_tf32_kernel, cudaFuncAttributeMaxDynamicSharedMemorySize,
                         GEMM_SMEM_BYTES);

    ln_kernel<<<S_TOK, 256>>>(x0, ln1_g, ln1_b, a);
    ln_kernel<<<S_TOK, 256>>>(x1, ln1_g, ln1_b, a + OFF);
    gemm_tf32_kernel<<<dim3(QKV_N / TBN, S2 / TBM), 256, GEMM_SMEM_BYTES>>>(
        a, attn_w, attn_b, nullptr, qkv, S2, QKV_N, DM, 0);
    attn_kernel<<<dim3(NB, NH, 4), 256, attn_smem>>>(qkv, qkv + (size_t)S_TOK * QKV_N,
                                                     attmp, attmp + OFF);
    gemm_tf32_kernel<<<dim3(DM / TBN, S_TOK / TBM), 256, GEMM_SMEM_BYTES>>>(
        attmp, proj_w, proj_b, x0, xa, S_TOK, DM, DM, 0);
    gemm_tf32_kernel<<<dim3(DM / TBN, S_TOK / TBM), 256, GEMM_SMEM_BYTES>>>(
        attmp + OFF, proj_w, proj_b, x1, xa + OFF, S_TOK, DM, DM, 0);
    ln_kernel<<<S2, 256>>>(xa, ln2_g, ln2_b, a);
    gemm_tf32_kernel<<<dim3(DI / TBN, S2 / TBM), 256, GEMM_SMEM_BYTES>>>(
        a, fc_w, fc_b, nullptr, hbuf, S2, DI, DM, 1);
    gemm_tf32_kernel<<<dim3(DM / TBN, S2 / TBM), 256, GEMM_SMEM_BYTES>>>(
        hbuf, mproj_w, mproj_b, xa, out, S2, DM, DI, 0);
    gemm_tf32_kernel<<<dim3((2 * DM) / TBN, S_TOK / TBM), 256, GEMM_SMEM_BYTES>>>(
        out + OFF, pose_fc_w, pose_fc_b, nullptr, ph, S_TOK, 2 * DM, DM, 1);
    pose_kernel<<<S_TOK, 256>>>(ph, pose_pw, pose_pb, out + 2 * OFF);
}

// round 10
// speedup vs baseline: 1.2468x; 1.0511x over previous
#include <cuda_runtime.h>
#include <math.h>
#include <stdint.h>

#define NB    20
#define BSZ   64
#define DM    768
#define NH    12
#define DI    3072
#define QKV_N (3*DM)          // 2304
#define S_TOK (2*NB*BSZ)      // 2560 tokens per stream
#define S2    (2*S_TOK)       // 5120 both streams

// ---------------- scratch (device globals; no allocation allowed) ----------
__device__ float g_a   [S2 * DM];
__device__ float g_qkv [S2 * QKV_N];
__device__ float g_attm[S2 * DM];
__device__ float g_xa  [S2 * DM];
__device__ float g_h   [S2 * DI];
__device__ float g_ph  [S_TOK * 2*DM];

// ---------------- common tf32 helpers --------------------------------------
__device__ __forceinline__ unsigned f2tf32(float f) {
    unsigned u;
    asm("cvt.rna.tf32.f32 %0, %1;" : "=r"(u) : "f"(f));
    return u;
}
__device__ __forceinline__ void tf32split(float x, float& hi, float& lo) {
    unsigned h = f2tf32(x);
    hi = __uint_as_float(h);
    lo = __uint_as_float(f2tf32(x - hi));
}

#define MMA_TF32(C, Ar, Br) \
    asm volatile( \
        "mma.sync.aligned.m16n8k8.row.col.f32.tf32.tf32.f32 " \
        "{%0,%1,%2,%3}, {%4,%5,%6,%7}, {%8,%9}, {%0,%1,%2,%3};" \
        : "+f"(C[0]), "+f"(C[1]), "+f"(C[2]), "+f"(C[3]) \
        : "r"(Ar[0]), "r"(Ar[1]), "r"(Ar[2]), "r"(Ar[3]), \
          "r"(Br[0]), "r"(Br[1]))

// ---------------- LayerNorm ------------------------------------------------
__global__ void ln_kernel(const float* __restrict__ x, const float* __restrict__ g,
                          const float* __restrict__ b, float* __restrict__ out) {
    int row = blockIdx.x;
    const float* xr = x + (size_t)row * DM;
    float* orow = out + (size_t)row * DM;
    int t = threadIdx.x;
    float v0 = xr[t], v1 = xr[t + 256], v2 = xr[t + 512];
    float s = v0 + v1 + v2;
    float ss = v0*v0 + v1*v1 + v2*v2;
    #pragma unroll
    for (int o = 16; o; o >>= 1) {
        s  += __shfl_xor_sync(0xffffffffu, s,  o);
        ss += __shfl_xor_sync(0xffffffffu, ss, o);
    }
    __shared__ float rs[8], rss[8];
    __shared__ float mean_s, rstd_s;
    int w = t >> 5;
    if ((t & 31) == 0) { rs[w] = s; rss[w] = ss; }
    __syncthreads();
    if (t == 0) {
        float S = 0.f, SS = 0.f;
        #pragma unroll
        for (int i = 0; i < 8; i++) { S += rs[i]; SS += rss[i]; }
        float m = S * (1.0f / 768.0f);
        float var = SS * (1.0f / 768.0f) - m * m;
        mean_s = m;
        rstd_s = rsqrtf(var + 1e-5f);
    }
    __syncthreads();
    float m = mean_s, r = rstd_s;
    orow[t]       = (v0 - m) * r * g[t]       + b[t];
    orow[t + 256] = (v1 - m) * r * g[t + 256] + b[t + 256];
    orow[t + 512] = (v2 - m) * r * g[t + 512] + b[t + 512];
}

// ---------------- 3xTF32 tensor-core GEMM (fp32-accurate, known-good R6) ---
#define TBM 128
#define TBN 64
#define TBK 16
#define ASTRIDE 20
#define BSTRIDE 72
#define ASZ (TBM * ASTRIDE)
#define BSZT (TBK * BSTRIDE)
#define GEMM_SMEM_BYTES ((2 * 2 * ASZ + 2 * 2 * BSZT) * 4)   // 59392

__global__ void __launch_bounds__(256)
gemm_tf32_kernel(const float* __restrict__ A, const float* __restrict__ B,
                 const float* __restrict__ bias, const float* __restrict__ resid,
                 float* __restrict__ C, int M, int N, int K, int act) {
    extern __shared__ float smem_dyn[];
    float* Asp[2][2];
    float* Bsp[2][2];
    #pragma unroll
    for (int bu = 0; bu < 2; bu++)
        #pragma unroll
        for (int p = 0; p < 2; p++) {
            Asp[bu][p] = smem_dyn + (bu * 2 + p) * ASZ;
            Bsp[bu][p] = smem_dyn + 4 * ASZ + (bu * 2 + p) * BSZT;
        }

    const int t = threadIdx.x;
    const int warp = t >> 5, lane = t & 31;
    const int g = lane >> 2, tig = lane & 3;
    const int wm = warp >> 1, wn = warp & 1;
    const int m0 = blockIdx.y * TBM, n0 = blockIdx.x * TBN;

    const int am0 = t >> 2,         akq0 = t & 3;
    const int am1 = (t + 256) >> 2, akq1 = t & 3;
    const int bk = t >> 4, bnq = t & 15;

    float c[2][4][4];
    #pragma unroll
    for (int i = 0; i < 2; i++)
        #pragma unroll
        for (int j = 0; j < 4; j++)
            #pragma unroll
            for (int r = 0; r < 4; r++) c[i][j][r] = 0.f;

    const int nIter = K / TBK;

    float4 ra0 = *(const float4*)&A[(size_t)(m0 + am0) * K + akq0 * 4];
    float4 ra1 = *(const float4*)&A[(size_t)(m0 + am1) * K + akq1 * 4];
    float4 rb  = *(const float4*)&B[(size_t)bk * N + n0 + bnq * 4];
    {
        const int ab0 = am0 * ASTRIDE + akq0 * 4;
        const int ab1 = am1 * ASTRIDE + akq1 * 4;
        const int bb  = bk * BSTRIDE + bnq * 4;
        float hi, lo;
        const float* pa0 = &ra0.x; const float* pa1 = &ra1.x; const float* pb = &rb.x;
        #pragma unroll
        for (int q = 0; q < 4; q++) {
            tf32split(pa0[q], hi, lo); Asp[0][0][ab0+q] = hi; Asp[0][1][ab0+q] = lo;
            tf32split(pa1[q], hi, lo); Asp[0][0][ab1+q] = hi; Asp[0][1][ab1+q] = lo;
            tf32split(pb[q],  hi, lo); Bsp[0][0][bb+q]  = hi; Bsp[0][1][bb+q]  = lo;
        }
    }
    __syncthreads();

    for (int it = 0; it < nIter; ++it) {
        const int buf = it & 1;
        if (it + 1 < nIter) {
            int k0 = (it + 1) * TBK;
            ra0 = *(const float4*)&A[(size_t)(m0 + am0) * K + k0 + akq0 * 4];
            ra1 = *(const float4*)&A[(size_t)(m0 + am1) * K + k0 + akq1 * 4];
            rb  = *(const float4*)&B[(size_t)(k0 + bk) * N + n0 + bnq * 4];
        }
        const unsigned* ash = (const unsigned*)Asp[buf][0];
        const unsigned* asl = (const unsigned*)Asp[buf][1];
        const unsigned* bsh = (const unsigned*)Bsp[buf][0];
        const unsigned* bsl = (const unsigned*)Bsp[buf][1];
        #pragma unroll
        for (int s = 0; s < 2; s++) {
            const int kb = s * 8;
            unsigned afh[2][4], afl[2][4], bfh[4][2], bfl[4][2];
            #pragma unroll
            for (int i = 0; i < 2; i++) {
                int mr = wm * 32 + i * 16;
                int i0 = (mr + g)     * ASTRIDE + kb + tig;
                int i1 = (mr + g + 8) * ASTRIDE + kb + tig;
                afh[i][0] = ash[i0];     afh[i][1] = ash[i1];
                afh[i][2] = ash[i0 + 4]; afh[i][3] = ash[i1 + 4];
                afl[i][0] = asl[i0];     afl[i][1] = asl[i1];
                afl[i][2] = asl[i0 + 4]; afl[i][3] = asl[i1 + 4];
            }
            #pragma unroll
            for (int j = 0; j < 4; j++) {
                int nb = wn * 32 + j * 8;
                int j0 = (kb + tig)     * BSTRIDE + nb + g;
                int j1 = (kb + tig + 4) * BSTRIDE + nb + g;
                bfh[j][0] = bsh[j0]; bfh[j][1] = bsh[j1];
                bfl[j][0] = bsl[j0]; bfl[j][1] = bsl[j1];
            }
            #pragma unroll
            for (int i = 0; i < 2; i++)
                #pragma unroll
                for (int j = 0; j < 4; j++) {
                    MMA_TF32(c[i][j], afl[i], bfh[j]);
                    MMA_TF32(c[i][j], afh[i], bfl[j]);
                    MMA_TF32(c[i][j], afh[i], bfh[j]);
                }
        }
        if (it + 1 < nIter) {
            const int nb2 = buf ^ 1;
            const int ab0 = am0 * ASTRIDE + akq0 * 4;
            const int ab1 = am1 * ASTRIDE + akq1 * 4;
            const int bb  = bk * BSTRIDE + bnq * 4;
            float hi, lo;
            const float* pa0 = &ra0.x; const float* pa1 = &ra1.x; const float* pb = &rb.x;
            #pragma unroll
            for (int q = 0; q < 4; q++) {
                tf32split(pa0[q], hi, lo); Asp[nb2][0][ab0+q] = hi; Asp[nb2][1][ab0+q] = lo;
                tf32split(pa1[q], hi, lo); Asp[nb2][0][ab1+q] = hi; Asp[nb2][1][ab1+q] = lo;
                tf32split(pb[q],  hi, lo); Bsp[nb2][0][bb+q]  = hi; Bsp[nb2][1][bb+q]  = lo;
            }
        }
        __syncthreads();
    }

    #pragma unroll
    for (int i = 0; i < 2; i++) {
        int r0 = m0 + wm * 32 + i * 16 + g;
        #pragma unroll
        for (int j = 0; j < 4; j++) {
            int col = n0 + wn * 32 + j * 8 + tig * 2;
            float b0 = bias[col], b1 = bias[col + 1];
            #pragma unroll
            for (int half = 0; half < 2; half++) {
                int row = r0 + half * 8;
                float v0 = c[i][j][half * 2 + 0] + b0;
                float v1 = c[i][j][half * 2 + 1] + b1;
                if (act == 1) {
                    v0 = 0.5f * v0 * (1.0f + erff(v0 * 0.70710678118654752440f));
                    v1 = 0.5f * v1 * (1.0f + erff(v1 * 0.70710678118654752440f));
                }
                if (resid) {
                    const float2 rr = *(const float2*)&resid[(size_t)row * N + col];
                    v0 += rr.x; v1 += rr.y;
                }
                float2 o; o.x = v0; o.y = v1;
                *(float2*)&C[(size_t)row * N + col] = o;
            }
        }
    }
}

// ---------------- Multiend block attention (tensor-core, 3xTF32) -----------
// One CTA per (stream e, batch b, head h, query-block i). 256 thr = 8 warps.
// Warp grid 4(wm: 16 query rows) x 2(wn: 32 cols). Strides: 68 for Q/K/P
// fragment loads (4g+tig distinct banks), 72 for V ((8tig+g) distinct).
// Scale 1/8 folded exactly into Q (power of two). Online softmax unchanged.
#define AQH 0
#define AQL 4352
#define AKVH 8704
#define AKVL 13312
#define ASS 17920
#define ASTATS 22272
#define ATT_SMEM_FLOATS (ASTATS + 192)
#define ATT_SMEM_BYTES (ATT_SMEM_FLOATS * 4)   // 89856

__global__ void __launch_bounds__(256)
attn_kernel(const float* __restrict__ qkv0, const float* __restrict__ qkv1,
            float* __restrict__ attm0, float* __restrict__ attm1) {
    extern __shared__ float sm[];
    float* q_hi  = sm + AQH;
    float* q_lo  = sm + AQL;
    float* kv_hi = sm + AKVH;
    float* kv_lo = sm + AKVL;
    float* s_s   = sm + ASS;
    float* m_s   = sm + ASTATS;
    float* l_s   = m_s + 64;
    float* al_s  = l_s + 64;

    const int i = blockIdx.x, h = blockIdx.y;
    const int e = blockIdx.z >> 1, b = blockIdx.z & 1;
    const float* qkvE = e ? qkv1 : qkv0;
    float* attm = e ? attm1 : attm0;
    const int t = threadIdx.x;
    const int warp = t >> 5, lane = t & 31;
    const int g = lane >> 2, tig = lane & 3;
    const int wm = warp & 3, wn = warp >> 2;
    const int qrow0 = (b * NB + i) * BSZ;
    const int ar = wm * 16;          // warp query-row base
    const int nb0 = wn * 32;         // warp col base (keys in S phase, dh in PV)

    // load Q (scaled by 1/8, exact) and split
    for (int idx = t; idx < 4096; idx += 256) {
        int qi = idx >> 6, d = idx & 63;
        float v = qkvE[(size_t)(qrow0 + qi) * QKV_N + DM + h * 64 + d] * 0.125f;
        float hi, lo;
        tf32split(v, hi, lo);
        q_hi[qi * 68 + d] = hi; q_lo[qi * 68 + d] = lo;
    }
    if (t < 64) { m_s[t] = -1e30f; l_s[t] = 0.f; }
    float acc[4][4] = {};

    for (int j = 0; j <= i; ++j) {
        const float* kvb = (j < i) ? qkv0 : qkvE;
        const int krow0 = (b * NB + j) * BSZ;
        __syncthreads();   // prev PV mma / Q stores / stats init complete
        // K tile -> kv (stride 68, [key][dh])
        for (int idx = t; idx < 4096; idx += 256) {
            int kj = idx >> 6, d = idx & 63;
            float v = kvb[(size_t)(krow0 + kj) * QKV_N + 2 * DM + h * 64 + d];
            float hi, lo;
            tf32split(v, hi, lo);
            kv_hi[kj * 68 + d] = hi; kv_lo[kj * 68 + d] = lo;
        }
        __syncthreads();
        // S = Q K^T via mma (3xTF32), K-dim = dh = 64
        float sv[4][4] = {};
        #pragma unroll
        for (int ks = 0; ks < 8; ks++) {
            const int kb = ks * 8;
            unsigned ah[4], al[4];
            int i0 = (ar + g) * 68 + kb + tig;
            int i1 = (ar + g + 8) * 68 + kb + tig;
            ah[0] = __float_as_uint(q_hi[i0]);     ah[1] = __float_as_uint(q_hi[i1]);
            ah[2] = __float_as_uint(q_hi[i0 + 4]); ah[3] = __float_as_uint(q_hi[i1 + 4]);
            al[0] = __float_as_uint(q_lo[i0]);     al[1] = __float_as_uint(q_lo[i1]);
            al[2] = __float_as_uint(q_lo[i0 + 4]); al[3] = __float_as_uint(q_lo[i1 + 4]);
            #pragma unroll
            for (int jt = 0; jt < 4; jt++) {
                int j0 = (nb0 + jt * 8 + g) * 68 + kb + tig;
                unsigned bh[2], bl[2];
                bh[0] = __float_as_uint(kv_hi[j0]); bh[1] = __float_as_uint(kv_hi[j0 + 4]);
                bl[0] = __float_as_uint(kv_lo[j0]); bl[1] = __float_as_uint(kv_lo[j0 + 4]);
                MMA_TF32(sv[jt], al, bh);
                MMA_TF32(sv[jt], ah, bl);
                MMA_TF32(sv[jt], ah, bh);
            }
        }
        // store S (already scaled)
        #pragma unroll
        for (int jt = 0; jt < 4; jt++) {
            int col = nb0 + jt * 8 + 2 * tig;
            float2 v01; v01.x = sv[jt][0]; v01.y = sv[jt][1];
            float2 v23; v23.x = sv[jt][2]; v23.y = sv[jt][3];
            *(float2*)&s_s[(ar + g) * 68 + col]     = v01;
            *(float2*)&s_s[(ar + g + 8) * 68 + col] = v23;
        }
        __syncthreads();
        // online softmax (4 lanes per row), then V load into kv
        {
            int q = t >> 2, p = t & 3;
            int base = q * 68 + p * 16;
            float lm = -1e30f;
            #pragma unroll
            for (int kk = 0; kk < 16; kk++) lm = fmaxf(lm, s_s[base + kk]);
            lm = fmaxf(lm, __shfl_xor_sync(0xffffffffu, lm, 1));
            lm = fmaxf(lm, __shfl_xor_sync(0xffffffffu, lm, 2));
            float mold = m_s[q];
            float mnew = fmaxf(mold, lm);
            float ls = 0.f;
            #pragma unroll
            for (int kk = 0; kk < 16; kk++) {
                float pp = __expf(s_s[base + kk] - mnew);
                s_s[base + kk] = pp;
                ls += pp;
            }
            ls += __shfl_xor_sync(0xffffffffu, ls, 1);
            ls += __shfl_xor_sync(0xffffffffu, ls, 2);
            if (p == 0) {
                float alpha = __expf(mold - mnew);
                al_s[q] = alpha;
                l_s[q] = l_s[q] * alpha + ls;
                m_s[q] = mnew;
            }
        }
        // V tile -> kv (stride 72, [key][dh]); kv's S-phase readers done (sync above)
        for (int idx = t; idx < 4096; idx += 256) {
            int kj = idx >> 6, d = idx & 63;
            float v = kvb[(size_t)(krow0 + kj) * QKV_N + h * 64 + d];
            float hi, lo;
            tf32split(v, hi, lo);
            kv_hi[kj * 72 + d] = hi; kv_lo[kj * 72 + d] = lo;
        }
        __syncthreads();
        // rescale + O += P V (3xTF32), K-dim = keys = 64
        {
            float a0 = al_s[ar + g], a1 = al_s[ar + g + 8];
            #pragma unroll
            for (int jt = 0; jt < 4; jt++) {
                acc[jt][0] *= a0; acc[jt][1] *= a0;
                acc[jt][2] *= a1; acc[jt][3] *= a1;
            }
        }
        #pragma unroll
        for (int ks = 0; ks < 8; ks++) {
            const int kb = ks * 8;
            int i0 = (ar + g) * 68 + kb + tig;
            int i1 = (ar + g + 8) * 68 + kb + tig;
            float p0 = s_s[i0], p1 = s_s[i1], p2 = s_s[i0 + 4], p3 = s_s[i1 + 4];
            unsigned ah[4], al[4];
            float hi, lo;
            tf32split(p0, hi, lo); ah[0] = __float_as_uint(hi); al[0] = __float_as_uint(lo);
            tf32split(p1, hi, lo); ah[1] = __float_as_uint(hi); al[1] = __float_as_uint(lo);
            tf32split(p2, hi, lo); ah[2] = __float_as_uint(hi); al[2] = __float_as_uint(lo);
            tf32split(p3, hi, lo); ah[3] = __float_as_uint(hi); al[3] = __float_as_uint(lo);
            #pragma unroll
            for (int jt = 0; jt < 4; jt++) {
                int nb = nb0 + jt * 8;
                int j0 = (kb + tig) * 72 + nb + g;
                int j1 = (kb + tig + 4) * 72 + nb + g;
                unsigned bh[2], bl[2];
                bh[0] = __float_as_uint(kv_hi[j0]); bh[1] = __float_as_uint(kv_hi[j1]);
                bl[0] = __float_as_uint(kv_lo[j0]); bl[1] = __float_as_uint(kv_lo[j1]);
                MMA_TF32(acc[jt], al, bh);
                MMA_TF32(acc[jt], ah, bl);
                MMA_TF32(acc[jt], ah, bh);
            }
        }
    }
    // epilogue: divide by l, write merged-head layout
    {
        const int r0 = ar + g, r1 = ar + g + 8;
        const float inv0 = 1.0f / l_s[r0], inv1 = 1.0f / l_s[r1];
        #pragma unroll
        for (int jt = 0; jt < 4; jt++) {
            int col = h * 64 + nb0 + jt * 8 + 2 * tig;
            float2 o0; o0.x = acc[jt][0] * inv0; o0.y = acc[jt][1] * inv0;
            float2 o1; o1.x = acc[jt][2] * inv1; o1.y = acc[jt][3] * inv1;
            *(float2*)&attm[(size_t)(qrow0 + r0) * DM + col] = o0;
            *(float2*)&attm[(size_t)(qrow0 + r1) * DM + col] = o1;
        }
    }
}

// ---------------- Pose projection + quaternion normalize -------------------
__global__ void pose_kernel(const float* __restrict__ ph, const float* __restrict__ w,
                            const float* __restrict__ bias, float* __restrict__ out) {
    int row = blockIdx.x;
    int t = threadIdx.x;
    const float* hr = ph + (size_t)row * (2 * DM);
    float part[7] = {};
    for (int j = t; j < 2 * DM; j += 256) {
        float hv = hr[j];
        #pragma unroll
        for (int o = 0; o < 7; o++) part[o] += hv * w[j * 7 + o];
    }
    #pragma unroll
    for (int o = 0; o < 7; o++)
        #pragma unroll
        for (int s = 16; s; s >>= 1)
            part[o] += __shfl_xor_sync(0xffffffffu, part[o], s);
    __shared__ float red[8][7];
    int wi = t >> 5;
    if ((t & 31) == 0)
        #pragma unroll
        for (int o = 0; o < 7; o++) red[wi][o] = part[o];
    __syncthreads();
    if (t == 0) {
        float hv[7];
        #pragma unroll
        for (int o = 0; o < 7; o++) {
            hv[o] = bias[o];
            for (int k = 0; k < 8; k++) hv[o] += red[k][o];
        }
        float q0 = hv[3], q1 = hv[4], q2 = hv[5], q3 = hv[6];
        float inv = rsqrtf(q0*q0 + q1*q1 + q2*q2 + q3*q3);
        q0 *= inv; q1 *= inv; q2 *= inv; q3 *= inv;
        if (q0 < 0.f) { q0 = -q0; q1 = -q1; q2 = -q2; q3 = -q3; }
        float* orow = out + (size_t)row * 7;
        orow[0] = hv[0]; orow[1] = hv[1]; orow[2] = hv[2];
        orow[3] = q0; orow[4] = q1; orow[5] = q2; orow[6] = q3;
    }
}

// ---------------------------------------------------------------------------
extern "C" void kernel_launch(void* const* d_in, const int* in_sizes, int n_in,
                              void* d_out, int out_size) {
    const float* x0        = (const float*)d_in[0];
    const float* x1        = (const float*)d_in[1];
    const float* ln1_g     = (const float*)d_in[2];
    const float* ln1_b     = (const float*)d_in[3];
    const float* attn_w    = (const float*)d_in[4];
    const float* attn_b    = (const float*)d_in[5];
    const float* proj_w    = (const float*)d_in[6];
    const float* proj_b    = (const float*)d_in[7];
    const float* ln2_g     = (const float*)d_in[8];
    const float* ln2_b     = (const float*)d_in[9];
    const float* fc_w      = (const float*)d_in[10];
    const float* fc_b      = (const float*)d_in[11];
    const float* mproj_w   = (const float*)d_in[12];
    const float* mproj_b   = (const float*)d_in[13];
    const float* pose_fc_w = (const float*)d_in[14];
    const float* pose_fc_b = (const float*)d_in[15];
    const float* pose_pw   = (const float*)d_in[16];
    const float* pose_pb   = (const float*)d_in[17];
    float* out = (float*)d_out;

    float *a, *qkv, *attmp, *xa, *hbuf, *ph;
    cudaGetSymbolAddress((void**)&a,     g_a);
    cudaGetSymbolAddress((void**)&qkv,   g_qkv);
    cudaGetSymbolAddress((void**)&attmp, g_attm);
    cudaGetSymbolAddress((void**)&xa,    g_xa);
    cudaGetSymbolAddress((void**)&hbuf,  g_h);
    cudaGetSymbolAddress((void**)&ph,    g_ph);

    const size_t OFF = (size_t)S_TOK * DM;
    cudaFuncSetAttribute(attn_kernel, cudaFuncAttributeMaxDynamicSharedMemorySize,
                         ATT_SMEM_BYTES);
    cudaFuncSetAttribute(gemm_tf32_kernel, cudaFuncAttributeMaxDynamicSharedMemorySize,
                         GEMM_SMEM_BYTES);

    ln_kernel<<<S_TOK, 256>>>(x0, ln1_g, ln1_b, a);
    ln_kernel<<<S_TOK, 256>>>(x1, ln1_g, ln1_b, a + OFF);
    gemm_tf32_kernel<<<dim3(QKV_N / TBN, S2 / TBM), 256, GEMM_SMEM_BYTES>>>(
        a, attn_w, attn_b, nullptr, qkv, S2, QKV_N, DM, 0);
    attn_kernel<<<dim3(NB, NH, 4), 256, ATT_SMEM_BYTES>>>(
        qkv, qkv + (size_t)S_TOK * QKV_N, attmp, attmp + OFF);
    gemm_tf32_kernel<<<dim3(DM / TBN, S_TOK / TBM), 256, GEMM_SMEM_BYTES>>>(
        attmp, proj_w, proj_b, x0, xa, S_TOK, DM, DM, 0);
    gemm_tf32_kernel<<<dim3(DM / TBN, S_TOK / TBM), 256, GEMM_SMEM_BYTES>>>(
        attmp + OFF, proj_w, proj_b, x1, xa + OFF, S_TOK, DM, DM, 0);
    ln_kernel<<<S2, 256>>>(xa, ln2_g, ln2_b, a);
    gemm_tf32_kernel<<<dim3(DI / TBN, S2 / TBM), 256, GEMM_SMEM_BYTES>>>(
        a, fc_w, fc_b, nullptr, hbuf, S2, DI, DM, 1);
    gemm_tf32_kernel<<<dim3(DM / TBN, S2 / TBM), 256, GEMM_SMEM_BYTES>>>(
        hbuf, mproj_w, mproj_b, xa, out, S2, DM, DI, 0);
    gemm_tf32_kernel<<<dim3((2 * DM) / TBN, S_TOK / TBM), 256, GEMM_SMEM_BYTES>>>(
        out + OFF, pose_fc_w, pose_fc_b, nullptr, ph, S_TOK, 2 * DM, DM, 1);
    pose_kernel<<<S_TOK, 256>>>(ph, pose_pw, pose_pb, out + 2 * OFF);
}

// round 11
// speedup vs baseline: 1.7567x; 1.4089x over previous
#include <cuda_runtime.h>
#include <math.h>
#include <stdint.h>

#define NB    20
#define BSZ   64
#define DM    768
#define NH    12
#define DI    3072
#define QKV_N (3*DM)          // 2304
#define S_TOK (2*NB*BSZ)      // 2560 tokens per stream
#define S2    (2*S_TOK)       // 5120 both streams

// ---------------- scratch (device globals; no allocation allowed) ----------
__device__ float g_a   [S2 * DM];
__device__ float g_qkv [S2 * QKV_N];
__device__ float g_attm[S2 * DM];
__device__ float g_xa  [S2 * DM];
__device__ float g_h   [S2 * DI];
__device__ float g_ph  [S_TOK * 2*DM];

// ---------------- common tf32 helpers --------------------------------------
__device__ __forceinline__ unsigned f2tf32(float f) {
    unsigned u;
    asm("cvt.rna.tf32.f32 %0, %1;" : "=r"(u) : "f"(f));
    return u;
}
__device__ __forceinline__ void tf32split(float x, float& hi, float& lo) {
    unsigned h = f2tf32(x);
    hi = __uint_as_float(h);
    lo = __uint_as_float(f2tf32(x - hi));
}
__device__ __forceinline__ void tf32split_u(float x, unsigned& hi, unsigned& lo) {
    hi = f2tf32(x);
    lo = f2tf32(x - __uint_as_float(hi));
}

#define MMA_TF32(C, Ar, Br) \
    asm volatile( \
        "mma.sync.aligned.m16n8k8.row.col.f32.tf32.tf32.f32 " \
        "{%0,%1,%2,%3}, {%4,%5,%6,%7}, {%8,%9}, {%0,%1,%2,%3};" \
        : "+f"(C[0]), "+f"(C[1]), "+f"(C[2]), "+f"(C[3]) \
        : "r"(Ar[0]), "r"(Ar[1]), "r"(Ar[2]), "r"(Ar[3]), \
          "r"(Br[0]), "r"(Br[1]))

// ---------------- LayerNorm ------------------------------------------------
__global__ void ln_kernel(const float* __restrict__ x, const float* __restrict__ g,
                          const float* __restrict__ b, float* __restrict__ out) {
    int row = blockIdx.x;
    const float* xr = x + (size_t)row * DM;
    float* orow = out + (size_t)row * DM;
    int t = threadIdx.x;
    float v0 = xr[t], v1 = xr[t + 256], v2 = xr[t + 512];
    float s = v0 + v1 + v2;
    float ss = v0*v0 + v1*v1 + v2*v2;
    #pragma unroll
    for (int o = 16; o; o >>= 1) {
        s  += __shfl_xor_sync(0xffffffffu, s,  o);
        ss += __shfl_xor_sync(0xffffffffu, ss, o);
    }
    __shared__ float rs[8], rss[8];
    __shared__ float mean_s, rstd_s;
    int w = t >> 5;
    if ((t & 31) == 0) { rs[w] = s; rss[w] = ss; }
    __syncthreads();
    if (t == 0) {
        float S = 0.f, SS = 0.f;
        #pragma unroll
        for (int i = 0; i < 8; i++) { S += rs[i]; SS += rss[i]; }
        float m = S * (1.0f / 768.0f);
        float var = SS * (1.0f / 768.0f) - m * m;
        mean_s = m;
        rstd_s = rsqrtf(var + 1e-5f);
    }
    __syncthreads();
    float m = mean_s, r = rstd_s;
    orow[t]       = (v0 - m) * r * g[t]       + b[t];
    orow[t + 256] = (v1 - m) * r * g[t + 256] + b[t + 256];
    orow[t + 512] = (v2 - m) * r * g[t + 512] + b[t + 512];
}

// ============ BIG-TILE 3xTF32 GEMM: CTA 128x128, 4 warps, warp 64x64 =======
// Raw fp32 tiles in smem; tf32 hi/lo split happens at fragment-read time.
// A row stride 20 floats (conflict-free frag reads); B row stride 136.
#define GBM 128
#define GBN 128
#define GBK 16
#define GAS 20
#define GBS 136
#define GASZ (GBM * GAS)   // 2560 floats
#define GBSZ (GBK * GBS)   // 2176 floats

__global__ void __launch_bounds__(128, 2)
gemm_big_kernel(const float* __restrict__ A, const float* __restrict__ B,
                const float* __restrict__ bias, const float* __restrict__ resid,
                float* __restrict__ C, int M, int N, int K, int act) {
    __shared__ float As[2][GASZ];
    __shared__ float Bs[2][GBSZ];

    const int t = threadIdx.x;
    const int warp = t >> 5, lane = t & 31;
    const int g = lane >> 2, tig = lane & 3;
    const int wm = warp >> 1, wn = warp & 1;          // 2x2 warp grid
    const int m0 = blockIdx.y * GBM, n0 = blockIdx.x * GBN;

    // load geometry: A tile 128x16 = 512 float4, idx=t+q*128 -> row=(t>>2)+q*32, kq=t&3
    const int arow = t >> 2, akq = t & 3;
    // B tile 16x128 = 512 float4, idx=t+q*128 -> row=(t>>5)+q*4, col4=t&31
    const int brow = t >> 5, bc4 = t & 31;

    float c[4][8][4];
    #pragma unroll
    for (int mb = 0; mb < 4; mb++)
        #pragma unroll
        for (int nb = 0; nb < 8; nb++)
            #pragma unroll
            for (int r = 0; r < 4; r++) c[mb][nb][r] = 0.f;

    const int nIter = K / GBK;

    float4 ra[4], rb[4];
    #pragma unroll
    for (int q = 0; q < 4; q++) {
        ra[q] = *(const float4*)&A[(size_t)(m0 + arow + q * 32) * K + akq * 4];
        rb[q] = *(const float4*)&B[(size_t)(brow + q * 4) * N + n0 + bc4 * 4];
    }
    #pragma unroll
    for (int q = 0; q < 4; q++) {
        *(float4*)&As[0][(arow + q * 32) * GAS + akq * 4] = ra[q];
        *(float4*)&Bs[0][(brow + q * 4) * GBS + bc4 * 4] = rb[q];
    }
    __syncthreads();

    for (int it = 0; it < nIter; ++it) {
        const int buf = it & 1;
        if (it + 1 < nIter) {
            int k0 = (it + 1) * GBK;
            #pragma unroll
            for (int q = 0; q < 4; q++) {
                ra[q] = *(const float4*)&A[(size_t)(m0 + arow + q * 32) * K + k0 + akq * 4];
                rb[q] = *(const float4*)&B[(size_t)(k0 + brow + q * 4) * N + n0 + bc4 * 4];
            }
        }
        const float* as = As[buf];
        const float* bs = Bs[buf];
        #pragma unroll
        for (int sub = 0; sub < 2; sub++) {
            const int kb = sub * 8;
            unsigned ah[4][4], al[4][4];
            #pragma unroll
            for (int mb = 0; mb < 4; mb++) {
                int base = (wm * 64 + mb * 16 + g) * GAS + kb + tig;
                float r0 = as[base];
                float r1 = as[base + 8 * GAS];
                float r2 = as[base + 4];
                float r3 = as[base + 8 * GAS + 4];
                tf32split_u(r0, ah[mb][0], al[mb][0]);
                tf32split_u(r1, ah[mb][1], al[mb][1]);
                tf32split_u(r2, ah[mb][2], al[mb][2]);
                tf32split_u(r3, ah[mb][3], al[mb][3]);
            }
            #pragma unroll
            for (int nb = 0; nb < 8; nb++) {
                int bb = (kb + tig) * GBS + wn * 64 + nb * 8 + g;
                float b0 = bs[bb];
                float b1 = bs[bb + 4 * GBS];
                unsigned bh[2], bl[2];
                tf32split_u(b0, bh[0], bl[0]);
                tf32split_u(b1, bh[1], bl[1]);
                #pragma unroll
                for (int mb = 0; mb < 4; mb++) {
                    MMA_TF32(c[mb][nb], al[mb], bh);
                    MMA_TF32(c[mb][nb], ah[mb], bl);
                    MMA_TF32(c[mb][nb], ah[mb], bh);
                }
            }
        }
        if (it + 1 < nIter) {
            const int b2 = buf ^ 1;
            #pragma unroll
            for (int q = 0; q < 4; q++) {
                *(float4*)&As[b2][(arow + q * 32) * GAS + akq * 4] = ra[q];
                *(float4*)&Bs[b2][(brow + q * 4) * GBS + bc4 * 4] = rb[q];
            }
        }
        __syncthreads();
    }

    // epilogue
    #pragma unroll
    for (int mb = 0; mb < 4; mb++) {
        int r0 = m0 + wm * 64 + mb * 16 + g;
        #pragma unroll
        for (int nb = 0; nb < 8; nb++) {
            int col = n0 + wn * 64 + nb * 8 + tig * 2;
            float b0 = bias[col], b1 = bias[col + 1];
            #pragma unroll
            for (int half = 0; half < 2; half++) {
                int row = r0 + half * 8;
                float v0 = c[mb][nb][half * 2 + 0] + b0;
                float v1 = c[mb][nb][half * 2 + 1] + b1;
                if (act == 1) {
                    v0 = 0.5f * v0 * (1.0f + erff(v0 * 0.70710678118654752440f));
                    v1 = 0.5f * v1 * (1.0f + erff(v1 * 0.70710678118654752440f));
                }
                if (resid) {
                    const float2 rr = *(const float2*)&resid[(size_t)row * N + col];
                    v0 += rr.x; v1 += rr.y;
                }
                float2 o; o.x = v0; o.y = v1;
                *(float2*)&C[(size_t)row * N + col] = o;
            }
        }
    }
}

// ---------------- 3xTF32 GEMM, 128x64 tile (known-good; used for proj) -----
#define TBM 128
#define TBN 64
#define TBK 16
#define ASTRIDE 20
#define BSTRIDE 72
#define ASZ (TBM * ASTRIDE)
#define BSZT (TBK * BSTRIDE)
#define GEMM_SMEM_BYTES ((2 * 2 * ASZ + 2 * 2 * BSZT) * 4)   // 59392

__global__ void __launch_bounds__(256)
gemm_tf32_kernel(const float* __restrict__ A, const float* __restrict__ B,
                 const float* __restrict__ bias, const float* __restrict__ resid,
                 float* __restrict__ C, int M, int N, int K, int act) {
    extern __shared__ float smem_dyn[];
    float* Asp[2][2];
    float* Bsp[2][2];
    #pragma unroll
    for (int bu = 0; bu < 2; bu++)
        #pragma unroll
        for (int p = 0; p < 2; p++) {
            Asp[bu][p] = smem_dyn + (bu * 2 + p) * ASZ;
            Bsp[bu][p] = smem_dyn + 4 * ASZ + (bu * 2 + p) * BSZT;
        }

    const int t = threadIdx.x;
    const int warp = t >> 5, lane = t & 31;
    const int g = lane >> 2, tig = lane & 3;
    const int wm = warp >> 1, wn = warp & 1;
    const int m0 = blockIdx.y * TBM, n0 = blockIdx.x * TBN;

    const int am0 = t >> 2,         akq0 = t & 3;
    const int am1 = (t + 256) >> 2, akq1 = t & 3;
    const int bk = t >> 4, bnq = t & 15;

    float c[2][4][4];
    #pragma unroll
    for (int i = 0; i < 2; i++)
        #pragma unroll
        for (int j = 0; j < 4; j++)
            #pragma unroll
            for (int r = 0; r < 4; r++) c[i][j][r] = 0.f;

    const int nIter = K / TBK;

    float4 ra0 = *(const float4*)&A[(size_t)(m0 + am0) * K + akq0 * 4];
    float4 ra1 = *(const float4*)&A[(size_t)(m0 + am1) * K + akq1 * 4];
    float4 rb  = *(const float4*)&B[(size_t)bk * N + n0 + bnq * 4];
    {
        const int ab0 = am0 * ASTRIDE + akq0 * 4;
        const int ab1 = am1 * ASTRIDE + akq1 * 4;
        const int bb  = bk * BSTRIDE + bnq * 4;
        float hi, lo;
        const float* pa0 = &ra0.x; const float* pa1 = &ra1.x; const float* pb = &rb.x;
        #pragma unroll
        for (int q = 0; q < 4; q++) {
            tf32split(pa0[q], hi, lo); Asp[0][0][ab0+q] = hi; Asp[0][1][ab0+q] = lo;
            tf32split(pa1[q], hi, lo); Asp[0][0][ab1+q] = hi; Asp[0][1][ab1+q] = lo;
            tf32split(pb[q],  hi, lo); Bsp[0][0][bb+q]  = hi; Bsp[0][1][bb+q]  = lo;
        }
    }
    __syncthreads();

    for (int it = 0; it < nIter; ++it) {
        const int buf = it & 1;
        if (it + 1 < nIter) {
            int k0 = (it + 1) * TBK;
            ra0 = *(const float4*)&A[(size_t)(m0 + am0) * K + k0 + akq0 * 4];
            ra1 = *(const float4*)&A[(size_t)(m0 + am1) * K + k0 + akq1 * 4];
            rb  = *(const float4*)&B[(size_t)(k0 + bk) * N + n0 + bnq * 4];
        }
        const unsigned* ash = (const unsigned*)Asp[buf][0];
        const unsigned* asl = (const unsigned*)Asp[buf][1];
        const unsigned* bsh = (const unsigned*)Bsp[buf][0];
        const unsigned* bsl = (const unsigned*)Bsp[buf][1];
        #pragma unroll
        for (int s = 0; s < 2; s++) {
            const int kb = s * 8;
            unsigned afh[2][4], afl[2][4], bfh[4][2], bfl[4][2];
            #pragma unroll
            for (int i = 0; i < 2; i++) {
                int mr = wm * 32 + i * 16;
                int i0 = (mr + g)     * ASTRIDE + kb + tig;
                int i1 = (mr + g + 8) * ASTRIDE + kb + tig;
                afh[i][0] = ash[i0];     afh[i][1] = ash[i1];
                afh[i][2] = ash[i0 + 4]; afh[i][3] = ash[i1 + 4];
                afl[i][0] = asl[i0];     afl[i][1] = asl[i1];
                afl[i][2] = asl[i0 + 4]; afl[i][3] = asl[i1 + 4];
            }
            #pragma unroll
            for (int j = 0; j < 4; j++) {
                int nb = wn * 32 + j * 8;
                int j0 = (kb + tig)     * BSTRIDE + nb + g;
                int j1 = (kb + tig + 4) * BSTRIDE + nb + g;
                bfh[j][0] = bsh[j0]; bfh[j][1] = bsh[j1];
                bfl[j][0] = bsl[j0]; bfl[j][1] = bsl[j1];
            }
            #pragma unroll
            for (int i = 0; i < 2; i++)
                #pragma unroll
                for (int j = 0; j < 4; j++) {
                    MMA_TF32(c[i][j], afl[i], bfh[j]);
                    MMA_TF32(c[i][j], afh[i], bfl[j]);
                    MMA_TF32(c[i][j], afh[i], bfh[j]);
                }
        }
        if (it + 1 < nIter) {
            const int nb2 = buf ^ 1;
            const int ab0 = am0 * ASTRIDE + akq0 * 4;
            const int ab1 = am1 * ASTRIDE + akq1 * 4;
            const int bb  = bk * BSTRIDE + bnq * 4;
            float hi, lo;
            const float* pa0 = &ra0.x; const float* pa1 = &ra1.x; const float* pb = &rb.x;
            #pragma unroll
            for (int q = 0; q < 4; q++) {
                tf32split(pa0[q], hi, lo); Asp[nb2][0][ab0+q] = hi; Asp[nb2][1][ab0+q] = lo;
                tf32split(pa1[q], hi, lo); Asp[nb2][0][ab1+q] = hi; Asp[nb2][1][ab1+q] = lo;
                tf32split(pb[q],  hi, lo); Bsp[nb2][0][bb+q]  = hi; Bsp[nb2][1][bb+q]  = lo;
            }
        }
        __syncthreads();
    }

    #pragma unroll
    for (int i = 0; i < 2; i++) {
        int r0 = m0 + wm * 32 + i * 16 + g;
        #pragma unroll
        for (int j = 0; j < 4; j++) {
            int col = n0 + wn * 32 + j * 8 + tig * 2;
            float b0 = bias[col], b1 = bias[col + 1];
            #pragma unroll
            for (int half = 0; half < 2; half++) {
                int row = r0 + half * 8;
                float v0 = c[i][j][half * 2 + 0] + b0;
                float v1 = c[i][j][half * 2 + 1] + b1;
                if (act == 1) {
                    v0 = 0.5f * v0 * (1.0f + erff(v0 * 0.70710678118654752440f));
                    v1 = 0.5f * v1 * (1.0f + erff(v1 * 0.70710678118654752440f));
                }
                if (resid) {
                    const float2 rr = *(const float2*)&resid[(size_t)row * N + col];
                    v0 += rr.x; v1 += rr.y;
                }
                float2 o; o.x = v0; o.y = v1;
                *(float2*)&C[(size_t)row * N + col] = o;
            }
        }
    }
}

// ---------------- Multiend block attention (tensor-core, 3xTF32) -----------
#define AQH 0
#define AQL 4352
#define AKVH 8704
#define AKVL 13312
#define ASS 17920
#define ASTATS 22272
#define ATT_SMEM_FLOATS (ASTATS + 192)
#define ATT_SMEM_BYTES (ATT_SMEM_FLOATS * 4)   // 89856

__global__ void __launch_bounds__(256)
attn_kernel(const float* __restrict__ qkv0, const float* __restrict__ qkv1,
            float* __restrict__ attm0, float* __restrict__ attm1) {
    extern __shared__ float sm[];
    float* q_hi  = sm + AQH;
    float* q_lo  = sm + AQL;
    float* kv_hi = sm + AKVH;
    float* kv_lo = sm + AKVL;
    float* s_s   = sm + ASS;
    float* m_s   = sm + ASTATS;
    float* l_s   = m_s + 64;
    float* al_s  = l_s + 64;

    const int i = blockIdx.x, h = blockIdx.y;
    const int e = blockIdx.z >> 1, b = blockIdx.z & 1;
    const float* qkvE = e ? qkv1 : qkv0;
    float* attm = e ? attm1 : attm0;
    const int t = threadIdx.x;
    const int warp = t >> 5, lane = t & 31;
    const int g = lane >> 2, tig = lane & 3;
    const int wm = warp & 3, wn = warp >> 2;
    const int qrow0 = (b * NB + i) * BSZ;
    const int ar = wm * 16;
    const int nb0 = wn * 32;

    for (int idx = t; idx < 4096; idx += 256) {
        int qi = idx >> 6, d = idx & 63;
        float v = qkvE[(size_t)(qrow0 + qi) * QKV_N + DM + h * 64 + d] * 0.125f;
        float hi, lo;
        tf32split(v, hi, lo);
        q_hi[qi * 68 + d] = hi; q_lo[qi * 68 + d] = lo;
    }
    if (t < 64) { m_s[t] = -1e30f; l_s[t] = 0.f; }
    float acc[4][4] = {};

    for (int j = 0; j <= i; ++j) {
        const float* kvb = (j < i) ? qkv0 : qkvE;
        const int krow0 = (b * NB + j) * BSZ;
        __syncthreads();
        for (int idx = t; idx < 4096; idx += 256) {
            int kj = idx >> 6, d = idx & 63;
            float v = kvb[(size_t)(krow0 + kj) * QKV_N + 2 * DM + h * 64 + d];
            float hi, lo;
            tf32split(v, hi, lo);
            kv_hi[kj * 68 + d] = hi; kv_lo[kj * 68 + d] = lo;
        }
        __syncthreads();
        float sv[4][4] = {};
        #pragma unroll
        for (int ks = 0; ks < 8; ks++) {
            const int kb = ks * 8;
            unsigned ah[4], al[4];
            int i0 = (ar + g) * 68 + kb + tig;
            int i1 = (ar + g + 8) * 68 + kb + tig;
            ah[0] = __float_as_uint(q_hi[i0]);     ah[1] = __float_as_uint(q_hi[i1]);
            ah[2] = __float_as_uint(q_hi[i0 + 4]); ah[3] = __float_as_uint(q_hi[i1 + 4]);
            al[0] = __float_as_uint(q_lo[i0]);     al[1] = __float_as_uint(q_lo[i1]);
            al[2] = __float_as_uint(q_lo[i0 + 4]); al[3] = __float_as_uint(q_lo[i1 + 4]);
            #pragma unroll
            for (int jt = 0; jt < 4; jt++) {
                int j0 = (nb0 + jt * 8 + g) * 68 + kb + tig;
                unsigned bh[2], bl[2];
                bh[0] = __float_as_uint(kv_hi[j0]); bh[1] = __float_as_uint(kv_hi[j0 + 4]);
                bl[0] = __float_as_uint(kv_lo[j0]); bl[1] = __float_as_uint(kv_lo[j0 + 4]);
                MMA_TF32(sv[jt], al, bh);
                MMA_TF32(sv[jt], ah, bl);
                MMA_TF32(sv[jt], ah, bh);
            }
        }
        #pragma unroll
        for (int jt = 0; jt < 4; jt++) {
            int col = nb0 + jt * 8 + 2 * tig;
            float2 v01; v01.x = sv[jt][0]; v01.y = sv[jt][1];
            float2 v23; v23.x = sv[jt][2]; v23.y = sv[jt][3];
            *(float2*)&s_s[(ar + g) * 68 + col]     = v01;
            *(float2*)&s_s[(ar + g + 8) * 68 + col] = v23;
        }
        __syncthreads();
        {
            int q = t >> 2, p = t & 3;
            int base = q * 68 + p * 16;
            float lm = -1e30f;
            #pragma unroll
            for (int kk = 0; kk < 16; kk++) lm = fmaxf(lm, s_s[base + kk]);
            lm = fmaxf(lm, __shfl_xor_sync(0xffffffffu, lm, 1));
            lm = fmaxf(lm, __shfl_xor_sync(0xffffffffu, lm, 2));
            float mold = m_s[q];
            float mnew = fmaxf(mold, lm);
            float ls = 0.f;
            #pragma unroll
            for (int kk = 0; kk < 16; kk++) {
                float pp = __expf(s_s[base + kk] - mnew);
                s_s[base + kk] = pp;
                ls += pp;
            }
            ls += __shfl_xor_sync(0xffffffffu, ls, 1);
            ls += __shfl_xor_sync(0xffffffffu, ls, 2);
            if (p == 0) {
                float alpha = __expf(mold - mnew);
                al_s[q] = alpha;
                l_s[q] = l_s[q] * alpha + ls;
                m_s[q] = mnew;
            }
        }
        for (int idx = t; idx < 4096; idx += 256) {
            int kj = idx >> 6, d = idx & 63;
            float v = kvb[(size_t)(krow0 + kj) * QKV_N + h * 64 + d];
            float hi, lo;
            tf32split(v, hi, lo);
            kv_hi[kj * 72 + d] = hi; kv_lo[kj * 72 + d] = lo;
        }
        __syncthreads();
        {
            float a0 = al_s[ar + g], a1 = al_s[ar + g + 8];
            #pragma unroll
            for (int jt = 0; jt < 4; jt++) {
                acc[jt][0] *= a0; acc[jt][1] *= a0;
                acc[jt][2] *= a1; acc[jt][3] *= a1;
            }
        }
        #pragma unroll
        for (int ks = 0; ks < 8; ks++) {
            const int kb = ks * 8;
            int i0 = (ar + g) * 68 + kb + tig;
            int i1 = (ar + g + 8) * 68 + kb + tig;
            float p0 = s_s[i0], p1 = s_s[i1], p2 = s_s[i0 + 4], p3 = s_s[i1 + 4];
            unsigned ah[4], al[4];
            float hi, lo;
            tf32split(p0, hi, lo); ah[0] = __float_as_uint(hi); al[0] = __float_as_uint(lo);
            tf32split(p1, hi, lo); ah[1] = __float_as_uint(hi); al[1] = __float_as_uint(lo);
            tf32split(p2, hi, lo); ah[2] = __float_as_uint(hi); al[2] = __float_as_uint(lo);
            tf32split(p3, hi, lo); ah[3] = __float_as_uint(hi); al[3] = __float_as_uint(lo);
            #pragma unroll
            for (int jt = 0; jt < 4; jt++) {
                int nb = nb0 + jt * 8;
                int j0 = (kb + tig) * 72 + nb + g;
                int j1 = (kb + tig + 4) * 72 + nb + g;
                unsigned bh[2], bl[2];
                bh[0] = __float_as_uint(kv_hi[j0]); bh[1] = __float_as_uint(kv_hi[j1]);
                bl[0] = __float_as_uint(kv_lo[j0]); bl[1] = __float_as_uint(kv_lo[j1]);
                MMA_TF32(acc[jt], al, bh);
                MMA_TF32(acc[jt], ah, bl);
                MMA_TF32(acc[jt], ah, bh);
            }
        }
    }
    {
        const int r0 = ar + g, r1 = ar + g + 8;
        const float inv0 = 1.0f / l_s[r0], inv1 = 1.0f / l_s[r1];
        #pragma unroll
        for (int jt = 0; jt < 4; jt++) {
            int col = h * 64 + nb0 + jt * 8 + 2 * tig;
            float2 o0; o0.x = acc[jt][0] * inv0; o0.y = acc[jt][1] * inv0;
            float2 o1; o1.x = acc[jt][2] * inv1; o1.y = acc[jt][3] * inv1;
            *(float2*)&attm[(size_t)(qrow0 + r0) * DM + col] = o0;
            *(float2*)&attm[(size_t)(qrow0 + r1) * DM + col] = o1;
        }
    }
}

// ---------------- Pose projection + quaternion normalize -------------------
__global__ void pose_kernel(const float* __restrict__ ph, const float* __restrict__ w,
                            const float* __restrict__ bias, float* __restrict__ out) {
    int row = blockIdx.x;
    int t = threadIdx.x;
    const float* hr = ph + (size_t)row * (2 * DM);
    float part[7] = {};
    for (int j = t; j < 2 * DM; j += 256) {
        float hv = hr[j];
        #pragma unroll
        for (int o = 0; o < 7; o++) part[o] += hv * w[j * 7 + o];
    }
    #pragma unroll
    for (int o = 0; o < 7; o++)
        #pragma unroll
        for (int s = 16; s; s >>= 1)
            part[o] += __shfl_xor_sync(0xffffffffu, part[o], s);
    __shared__ float red[8][7];
    int wi = t >> 5;
    if ((t & 31) == 0)
        #pragma unroll
        for (int o = 0; o < 7; o++) red[wi][o] = part[o];
    __syncthreads();
    if (t == 0) {
        float hv[7];
        #pragma unroll
        for (int o = 0; o < 7; o++) {
            hv[o] = bias[o];
            for (int k = 0; k < 8; k++) hv[o] += red[k][o];
        }
        float q0 = hv[3], q1 = hv[4], q2 = hv[5], q3 = hv[6];
        float inv = rsqrtf(q0*q0 + q1*q1 + q2*q2 + q3*q3);
        q0 *= inv; q1 *= inv; q2 *= inv; q3 *= inv;
        if (q0 < 0.f) { q0 = -q0; q1 = -q1; q2 = -q2; q3 = -q3; }
        float* orow = out + (size_t)row * 7;
        orow[0] = hv[0]; orow[1] = hv[1]; orow[2] = hv[2];
        orow[3] = q0; orow[4] = q1; orow[5] = q2; orow[6] = q3;
    }
}

// ---------------------------------------------------------------------------
extern "C" void kernel_launch(void* const* d_in, const int* in_sizes, int n_in,
                              void* d_out, int out_size) {
    const float* x0        = (const float*)d_in[0];
    const float* x1        = (const float*)d_in[1];
    const float* ln1_g     = (const float*)d_in[2];
    const float* ln1_b     = (const float*)d_in[3];
    const float* attn_w    = (const float*)d_in[4];
    const float* attn_b    = (const float*)d_in[5];
    const float* proj_w    = (const float*)d_in[6];
    const float* proj_b    = (const float*)d_in[7];
    const float* ln2_g     = (const float*)d_in[8];
    const float* ln2_b     = (const float*)d_in[9];
    const float* fc_w      = (const float*)d_in[10];
    const float* fc_b      = (const float*)d_in[11];
    const float* mproj_w   = (const float*)d_in[12];
    const float* mproj_b   = (const float*)d_in[13];
    const float* pose_fc_w = (const float*)d_in[14];
    const float* pose_fc_b = (const float*)d_in[15];
    const float* pose_pw   = (const float*)d_in[16];
    const float* pose_pb   = (const float*)d_in[17];
    float* out = (float*)d_out;

    float *a, *qkv, *attmp, *xa, *hbuf, *ph;
    cudaGetSymbolAddress((void**)&a,     g_a);
    cudaGetSymbolAddress((void**)&qkv,   g_qkv);
    cudaGetSymbolAddress((void**)&attmp, g_attm);
    cudaGetSymbolAddress((void**)&xa,    g_xa);
    cudaGetSymbolAddress((void**)&hbuf,  g_h);
    cudaGetSymbolAddress((void**)&ph,    g_ph);

    const size_t OFF = (size_t)S_TOK * DM;
    cudaFuncSetAttribute(attn_kernel, cudaFuncAttributeMaxDynamicSharedMemorySize,
                         ATT_SMEM_BYTES);
    cudaFuncSetAttribute(gemm_tf32_kernel, cudaFuncAttributeMaxDynamicSharedMemorySize,
                         GEMM_SMEM_BYTES);

    ln_kernel<<<S_TOK, 256>>>(x0, ln1_g, ln1_b, a);
    ln_kernel<<<S_TOK, 256>>>(x1, ln1_g, ln1_b, a + OFF);
    // QKV (big-tile)
    gemm_big_kernel<<<dim3(QKV_N / GBN, S2 / GBM), 128>>>(
        a, attn_w, attn_b, nullptr, qkv, S2, QKV_N, DM, 0);
    attn_kernel<<<dim3(NB, NH, 4), 256, ATT_SMEM_BYTES>>>(
        qkv, qkv + (size_t)S_TOK * QKV_N, attmp, attmp + OFF);
    // attn out projection + residual (small N -> old kernel)
    gemm_tf32_kernel<<<dim3(DM / TBN, S_TOK / TBM), 256, GEMM_SMEM_BYTES>>>(
        attmp, proj_w, proj_b, x0, xa, S_TOK, DM, DM, 0);
    gemm_tf32_kernel<<<dim3(DM / TBN, S_TOK / TBM), 256, GEMM_SMEM_BYTES>>>(
        attmp + OFF, proj_w, proj_b, x1, xa + OFF, S_TOK, DM, DM, 0);
    ln_kernel<<<S2, 256>>>(xa, ln2_g, ln2_b, a);
    // MLP (big-tile)
    gemm_big_kernel<<<dim3(DI / GBN, S2 / GBM), 128>>>(
        a, fc_w, fc_b, nullptr, hbuf, S2, DI, DM, 1);
    gemm_big_kernel<<<dim3(DM / GBN, S2 / GBM), 128>>>(
        hbuf, mproj_w, mproj_b, xa, out, S2, DM, DI, 0);
    // pose head (big-tile)
    gemm_big_kernel<<<dim3((2 * DM) / GBN, S_TOK / GBM), 128>>>(
        out + OFF, pose_fc_w, pose_fc_b, nullptr, ph, S_TOK, 2 * DM, DM, 1);
    pose_kernel<<<S_TOK, 256>>>(ph, pose_pw, pose_pb, out + 2 * OFF);
}

// round 14
// speedup vs baseline: 1.8072x; 1.0288x over previous
#include <cuda_runtime.h>
#include <math.h>
#include <stdint.h>

#define NB    20
#define BSZ   64
#define DM    768
#define NH    12
#define DI    3072
#define QKV_N (3*DM)          // 2304
#define S_TOK (2*NB*BSZ)      // 2560 tokens per stream
#define S2    (2*S_TOK)       // 5120 both streams

// ---------------- scratch (device globals; no allocation allowed) ----------
__device__ float g_a   [S2 * DM];
__device__ float g_qkv [S2 * QKV_N];
__device__ float g_attm[S2 * DM];
__device__ float g_xa  [S2 * DM];
__device__ float g_h   [S2 * DI];
__device__ float g_ph  [S_TOK * 2*DM];

// ---------------- common tf32 helpers --------------------------------------
__device__ __forceinline__ unsigned f2tf32(float f) {
    unsigned u;
    asm("cvt.rna.tf32.f32 %0, %1;" : "=r"(u) : "f"(f));
    return u;
}
__device__ __forceinline__ void tf32split(float x, float& hi, float& lo) {
    unsigned h = f2tf32(x);
    hi = __uint_as_float(h);
    lo = __uint_as_float(f2tf32(x - hi));
}
__device__ __forceinline__ void tf32split_u(float x, unsigned& hi, unsigned& lo) {
    hi = f2tf32(x);
    lo = f2tf32(x - __uint_as_float(hi));
}

#define MMA_TF32(C, Ar, Br) \
    asm volatile( \
        "mma.sync.aligned.m16n8k8.row.col.f32.tf32.tf32.f32 " \
        "{%0,%1,%2,%3}, {%4,%5,%6,%7}, {%8,%9}, {%0,%1,%2,%3};" \
        : "+f"(C[0]), "+f"(C[1]), "+f"(C[2]), "+f"(C[3]) \
        : "r"(Ar[0]), "r"(Ar[1]), "r"(Ar[2]), "r"(Ar[3]), \
          "r"(Br[0]), "r"(Br[1]))

// ---------------- LayerNorm ------------------------------------------------
__global__ void ln_kernel(const float* __restrict__ x, const float* __restrict__ g,
                          const float* __restrict__ b, float* __restrict__ out) {
    int row = blockIdx.x;
    const float* xr = x + (size_t)row * DM;
    float* orow = out + (size_t)row * DM;
    int t = threadIdx.x;
    float v0 = xr[t], v1 = xr[t + 256], v2 = xr[t + 512];
    float s = v0 + v1 + v2;
    float ss = v0*v0 + v1*v1 + v2*v2;
    #pragma unroll
    for (int o = 16; o; o >>= 1) {
        s  += __shfl_xor_sync(0xffffffffu, s,  o);
        ss += __shfl_xor_sync(0xffffffffu, ss, o);
    }
    __shared__ float rs[8], rss[8];
    __shared__ float mean_s, rstd_s;
    int w = t >> 5;
    if ((t & 31) == 0) { rs[w] = s; rss[w] = ss; }
    __syncthreads();
    if (t == 0) {
        float S = 0.f, SS = 0.f;
        #pragma unroll
        for (int i = 0; i < 8; i++) { S += rs[i]; SS += rss[i]; }
        float m = S * (1.0f / 768.0f);
        float var = SS * (1.0f / 768.0f) - m * m;
        mean_s = m;
        rstd_s = rsqrtf(var + 1e-5f);
    }
    __syncthreads();
    float m = mean_s, r = rstd_s;
    orow[t]       = (v0 - m) * r * g[t]       + b[t];
    orow[t + 256] = (v1 - m) * r * g[t + 256] + b[t + 256];
    orow[t + 512] = (v2 - m) * r * g[t + 512] + b[t + 512];
}

// ============ BIG-TILE 3xTF32 GEMM: CTA 128x128, 4 warps, warp 64x64 =======
// Raw fp32 tiles in smem; tf32 hi/lo split at fragment-read time.
// Term-major MMA order (all mb for term0, then term1, term2) -> RAW distance 4.
#define GBM 128
#define GBN 128
#define GBK 16
#define GAS 20
#define GBS 136
#define GASZ (GBM * GAS)   // 2560 floats
#define GBSZ (GBK * GBS)   // 2176 floats

__global__ void __launch_bounds__(128, 2)
gemm_big_kernel(const float* __restrict__ A, const float* __restrict__ B,
                const float* __restrict__ bias, const float* __restrict__ resid,
                float* __restrict__ C, int M, int N, int K, int act) {
    __shared__ float As[2][GASZ];
    __shared__ float Bs[2][GBSZ];

    const int t = threadIdx.x;
    const int warp = t >> 5, lane = t & 31;
    const int g = lane >> 2, tig = lane & 3;
    const int wm = warp >> 1, wn = warp & 1;          // 2x2 warp grid
    const int m0 = blockIdx.y * GBM, n0 = blockIdx.x * GBN;

    const int arow = t >> 2, akq = t & 3;
    const int brow = t >> 5, bc4 = t & 31;

    float c[4][8][4];
    #pragma unroll
    for (int mb = 0; mb < 4; mb++)
        #pragma unroll
        for (int nb = 0; nb < 8; nb++)
            #pragma unroll
            for (int r = 0; r < 4; r++) c[mb][nb][r] = 0.f;

    const int nIter = K / GBK;

    float4 ra[4], rb[4];
    #pragma unroll
    for (int q = 0; q < 4; q++) {
        ra[q] = *(const float4*)&A[(size_t)(m0 + arow + q * 32) * K + akq * 4];
        rb[q] = *(const float4*)&B[(size_t)(brow + q * 4) * N + n0 + bc4 * 4];
    }
    #pragma unroll
    for (int q = 0; q < 4; q++) {
        *(float4*)&As[0][(arow + q * 32) * GAS + akq * 4] = ra[q];
        *(float4*)&Bs[0][(brow + q * 4) * GBS + bc4 * 4] = rb[q];
    }
    __syncthreads();

    for (int it = 0; it < nIter; ++it) {
        const int buf = it & 1;
        if (it + 1 < nIter) {
            int k0 = (it + 1) * GBK;
            #pragma unroll
            for (int q = 0; q < 4; q++) {
                ra[q] = *(const float4*)&A[(size_t)(m0 + arow + q * 32) * K + k0 + akq * 4];
                rb[q] = *(const float4*)&B[(size_t)(k0 + brow + q * 4) * N + n0 + bc4 * 4];
            }
        }
        const float* as = As[buf];
        const float* bs = Bs[buf];
        #pragma unroll
        for (int sub = 0; sub < 2; sub++) {
            const int kb = sub * 8;
            unsigned ah[4][4], al[4][4];
            #pragma unroll
            for (int mb = 0; mb < 4; mb++) {
                int base = (wm * 64 + mb * 16 + g) * GAS + kb + tig;
                tf32split_u(as[base],                ah[mb][0], al[mb][0]);
                tf32split_u(as[base + 8 * GAS],      ah[mb][1], al[mb][1]);
                tf32split_u(as[base + 4],            ah[mb][2], al[mb][2]);
                tf32split_u(as[base + 8 * GAS + 4],  ah[mb][3], al[mb][3]);
            }
            #pragma unroll
            for (int nb = 0; nb < 8; nb++) {
                int bb = (kb + tig) * GBS + wn * 64 + nb * 8 + g;
                unsigned bh[2], bl[2];
                tf32split_u(bs[bb],           bh[0], bl[0]);
                tf32split_u(bs[bb + 4 * GBS], bh[1], bl[1]);
                // term-major: all 4 mb per term -> consecutive MMAs independent
                #pragma unroll
                for (int mb = 0; mb < 4; mb++) MMA_TF32(c[mb][nb], al[mb], bh);
                #pragma unroll
                for (int mb = 0; mb < 4; mb++) MMA_TF32(c[mb][nb], ah[mb], bl);
                #pragma unroll
                for (int mb = 0; mb < 4; mb++) MMA_TF32(c[mb][nb], ah[mb], bh);
            }
        }
        if (it + 1 < nIter) {
            const int b2 = buf ^ 1;
            #pragma unroll
            for (int q = 0; q < 4; q++) {
                *(float4*)&As[b2][(arow + q * 32) * GAS + akq * 4] = ra[q];
                *(float4*)&Bs[b2][(brow + q * 4) * GBS + bc4 * 4] = rb[q];
            }
        }
        __syncthreads();
    }

    // epilogue
    #pragma unroll
    for (int mb = 0; mb < 4; mb++) {
        int r0 = m0 + wm * 64 + mb * 16 + g;
        #pragma unroll
        for (int nb = 0; nb < 8; nb++) {
            int col = n0 + wn * 64 + nb * 8 + tig * 2;
            float b0 = bias[col], b1 = bias[col + 1];
            #pragma unroll
            for (int half = 0; half < 2; half++) {
                int row = r0 + half * 8;
                float v0 = c[mb][nb][half * 2 + 0] + b0;
                float v1 = c[mb][nb][half * 2 + 1] + b1;
                if (act == 1) {
                    v0 = 0.5f * v0 * (1.0f + erff(v0 * 0.70710678118654752440f));
                    v1 = 0.5f * v1 * (1.0f + erff(v1 * 0.70710678118654752440f));
                }
                if (resid) {
                    const float2 rr = *(const float2*)&resid[(size_t)row * N + col];
                    v0 += rr.x; v1 += rr.y;
                }
                float2 o; o.x = v0; o.y = v1;
                *(float2*)&C[(size_t)row * N + col] = o;
            }
        }
    }
}

// ---------------- Multiend block attention (tensor-core, 3xTF32) -----------
#define AQH 0
#define AQL 4352
#define AKVH 8704
#define AKVL 13312
#define ASS 17920
#define ASTATS 22272
#define ATT_SMEM_FLOATS (ASTATS + 192)
#define ATT_SMEM_BYTES (ATT_SMEM_FLOATS * 4)   // 89856

__global__ void __launch_bounds__(256)
attn_kernel(const float* __restrict__ qkv0, const float* __restrict__ qkv1,
            float* __restrict__ attm0, float* __restrict__ attm1) {
    extern __shared__ float sm[];
    float* q_hi  = sm + AQH;
    float* q_lo  = sm + AQL;
    float* kv_hi = sm + AKVH;
    float* kv_lo = sm + AKVL;
    float* s_s   = sm + ASS;
    float* m_s   = sm + ASTATS;
    float* l_s   = m_s + 64;
    float* al_s  = l_s + 64;

    const int i = blockIdx.x, h = blockIdx.y;
    const int e = blockIdx.z >> 1, b = blockIdx.z & 1;
    const float* qkvE = e ? qkv1 : qkv0;
    float* attm = e ? attm1 : attm0;
    const int t = threadIdx.x;
    const int warp = t >> 5, lane = t & 31;
    const int g = lane >> 2, tig = lane & 3;
    const int wm = warp & 3, wn = warp >> 2;
    const int qrow0 = (b * NB + i) * BSZ;
    const int ar = wm * 16;
    const int nb0 = wn * 32;

    for (int idx = t; idx < 4096; idx += 256) {
        int qi = idx >> 6, d = idx & 63;
        float v = qkvE[(size_t)(qrow0 + qi) * QKV_N + DM + h * 64 + d] * 0.125f;
        float hi, lo;
        tf32split(v, hi, lo);
        q_hi[qi * 68 + d] = hi; q_lo[qi * 68 + d] = lo;
    }
    if (t < 64) { m_s[t] = -1e30f; l_s[t] = 0.f; }
    float acc[4][4] = {};

    for (int j = 0; j <= i; ++j) {
        const float* kvb = (j < i) ? qkv0 : qkvE;
        const int krow0 = (b * NB + j) * BSZ;
        __syncthreads();
        for (int idx = t; idx < 4096; idx += 256) {
            int kj = idx >> 6, d = idx & 63;
            float v = kvb[(size_t)(krow0 + kj) * QKV_N + 2 * DM + h * 64 + d];
            float hi, lo;
            tf32split(v, hi, lo);
            kv_hi[kj * 68 + d] = hi; kv_lo[kj * 68 + d] = lo;
        }
        __syncthreads();
        float sv[4][4] = {};
        #pragma unroll
        for (int ks = 0; ks < 8; ks++) {
            const int kb = ks * 8;
            unsigned ah[4], al[4];
            int i0 = (ar + g) * 68 + kb + tig;
            int i1 = (ar + g + 8) * 68 + kb + tig;
            ah[0] = __float_as_uint(q_hi[i0]);     ah[1] = __float_as_uint(q_hi[i1]);
            ah[2] = __float_as_uint(q_hi[i0 + 4]); ah[3] = __float_as_uint(q_hi[i1 + 4]);
            al[0] = __float_as_uint(q_lo[i0]);     al[1] = __float_as_uint(q_lo[i1]);
            al[2] = __float_as_uint(q_lo[i0 + 4]); al[3] = __float_as_uint(q_lo[i1 + 4]);
            unsigned bh[4][2], bl[4][2];
            #pragma unroll
            for (int jt = 0; jt < 4; jt++) {
                int j0 = (nb0 + jt * 8 + g) * 68 + kb + tig;
                bh[jt][0] = __float_as_uint(kv_hi[j0]); bh[jt][1] = __float_as_uint(kv_hi[j0 + 4]);
                bl[jt][0] = __float_as_uint(kv_lo[j0]); bl[jt][1] = __float_as_uint(kv_lo[j0 + 4]);
            }
            // term-major across jt
            #pragma unroll
            for (int jt = 0; jt < 4; jt++) MMA_TF32(sv[jt], al, bh[jt]);
            #pragma unroll
            for (int jt = 0; jt < 4; jt++) MMA_TF32(sv[jt], ah, bl[jt]);
            #pragma unroll
            for (int jt = 0; jt < 4; jt++) MMA_TF32(sv[jt], ah, bh[jt]);
        }
        #pragma unroll
        for (int jt = 0; jt < 4; jt++) {
            int col = nb0 + jt * 8 + 2 * tig;
            float2 v01; v01.x = sv[jt][0]; v01.y = sv[jt][1];
            float2 v23; v23.x = sv[jt][2]; v23.y = sv[jt][3];
            *(float2*)&s_s[(ar + g) * 68 + col]     = v01;
            *(float2*)&s_s[(ar + g + 8) * 68 + col] = v23;
        }
        __syncthreads();
        {
            int q = t >> 2, p = t & 3;
            int base = q * 68 + p * 16;
            float lm = -1e30f;
            #pragma unroll
            for (int kk = 0; kk < 16; kk++) lm = fmaxf(lm, s_s[base + kk]);
            lm = fmaxf(lm, __shfl_xor_sync(0xffffffffu, lm, 1));
            lm = fmaxf(lm, __shfl_xor_sync(0xffffffffu, lm, 2));
            float mold = m_s[q];
            float mnew = fmaxf(mold, lm);
            float ls = 0.f;
            #pragma unroll
            for (int kk = 0; kk < 16; kk++) {
                float pp = __expf(s_s[base + kk] - mnew);
                s_s[base + kk] = pp;
                ls += pp;
            }
            ls += __shfl_xor_sync(0xffffffffu, ls, 1);
            ls += __shfl_xor_sync(0xffffffffu, ls, 2);
            if (p == 0) {
                float alpha = __expf(mold - mnew);
                al_s[q] = alpha;
                l_s[q] = l_s[q] * alpha + ls;
                m_s[q] = mnew;
            }
        }
        for (int idx = t; idx < 4096; idx += 256) {
            int kj = idx >> 6, d = idx & 63;
            float v = kvb[(size_t)(krow0 + kj) * QKV_N + h * 64 + d];
            float hi, lo;
            tf32split(v, hi, lo);
            kv_hi[kj * 72 + d] = hi; kv_lo[kj * 72 + d] = lo;
        }
        __syncthreads();
        {
            float a0 = al_s[ar + g], a1 = al_s[ar + g + 8];
            #pragma unroll
            for (int jt = 0; jt < 4; jt++) {
                acc[jt][0] *= a0; acc[jt][1] *= a0;
                acc[jt][2] *= a1; acc[jt][3] *= a1;
            }
        }
        #pragma unroll
        for (int ks = 0; ks < 8; ks++) {
            const int kb = ks * 8;
            int i0 = (ar + g) * 68 + kb + tig;
            int i1 = (ar + g + 8) * 68 + kb + tig;
            unsigned ah[4], al[4];
            tf32split_u(s_s[i0],     ah[0], al[0]);
            tf32split_u(s_s[i1],     ah[1], al[1]);
            tf32split_u(s_s[i0 + 4], ah[2], al[2]);
            tf32split_u(s_s[i1 + 4], ah[3], al[3]);
            unsigned bh[4][2], bl[4][2];
            #pragma unroll
            for (int jt = 0; jt < 4; jt++) {
                int nb = nb0 + jt * 8;
                int j0 = (kb + tig) * 72 + nb + g;
                int j1 = (kb + tig + 4) * 72 + nb + g;
                bh[jt][0] = __float_as_uint(kv_hi[j0]); bh[jt][1] = __float_as_uint(kv_hi[j1]);
                bl[jt][0] = __float_as_uint(kv_lo[j0]); bl[jt][1] = __float_as_uint(kv_lo[j1]);
            }
            #pragma unroll
            for (int jt = 0; jt < 4; jt++) MMA_TF32(acc[jt], al, bh[jt]);
            #pragma unroll
            for (int jt = 0; jt < 4; jt++) MMA_TF32(acc[jt], ah, bl[jt]);
            #pragma unroll
            for (int jt = 0; jt < 4; jt++) MMA_TF32(acc[jt], ah, bh[jt]);
        }
    }
    {
        const int r0 = ar + g, r1 = ar + g + 8;
        const float inv0 = 1.0f / l_s[r0], inv1 = 1.0f / l_s[r1];
        #pragma unroll
        for (int jt = 0; jt < 4; jt++) {
            int col = h * 64 + nb0 + jt * 8 + 2 * tig;
            float2 o0; o0.x = acc[jt][0] * inv0; o0.y = acc[jt][1] * inv0;
            float2 o1; o1.x = acc[jt][2] * inv1; o1.y = acc[jt][3] * inv1;
            *(float2*)&attm[(size_t)(qrow0 + r0) * DM + col] = o0;
            *(float2*)&attm[(size_t)(qrow0 + r1) * DM + col] = o1;
        }
    }
}

// ---------------- Pose projection + quaternion normalize -------------------
__global__ void pose_kernel(const float* __restrict__ ph, const float* __restrict__ w,
                            const float* __restrict__ bias, float* __restrict__ out) {
    int row = blockIdx.x;
    int t = threadIdx.x;
    const float* hr = ph + (size_t)row * (2 * DM);
    float part[7] = {};
    for (int j = t; j < 2 * DM; j += 256) {
        float hv = hr[j];
        #pragma unroll
        for (int o = 0; o < 7; o++) part[o] += hv * w[j * 7 + o];
    }
    #pragma unroll
    for (int o = 0; o < 7; o++)
        #pragma unroll
        for (int s = 16; s; s >>= 1)
            part[o] += __shfl_xor_sync(0xffffffffu, part[o], s);
    __shared__ float red[8][7];
    int wi = t >> 5;
    if ((t & 31) == 0)
        #pragma unroll
        for (int o = 0; o < 7; o++) red[wi][o] = part[o];
    __syncthreads();
    if (t == 0) {
        float hv[7];
        #pragma unroll
        for (int o = 0; o < 7; o++) {
            hv[o] = bias[o];
            for (int k = 0; k < 8; k++) hv[o] += red[k][o];
        }
        float q0 = hv[3], q1 = hv[4], q2 = hv[5], q3 = hv[6];
        float inv = rsqrtf(q0*q0 + q1*q1 + q2*q2 + q3*q3);
        q0 *= inv; q1 *= inv; q2 *= inv; q3 *= inv;
        if (q0 < 0.f) { q0 = -q0; q1 = -q1; q2 = -q2; q3 = -q3; }
        float* orow = out + (size_t)row * 7;
        orow[0] = hv[0]; orow[1] = hv[1]; orow[2] = hv[2];
        orow[3] = q0; orow[4] = q1; orow[5] = q2; orow[6] = q3;
    }
}

// ---------------------------------------------------------------------------
extern "C" void kernel_launch(void* const* d_in, const int* in_sizes, int n_in,
                              void* d_out, int out_size) {
    const float* x0        = (const float*)d_in[0];
    const float* x1        = (const float*)d_in[1];
    const float* ln1_g     = (const float*)d_in[2];
    const float* ln1_b     = (const float*)d_in[3];
    const float* attn_w    = (const float*)d_in[4];
    const float* attn_b    = (const float*)d_in[5];
    const float* proj_w    = (const float*)d_in[6];
    const float* proj_b    = (const float*)d_in[7];
    const float* ln2_g     = (const float*)d_in[8];
    const float* ln2_b     = (const float*)d_in[9];
    const float* fc_w      = (const float*)d_in[10];
    const float* fc_b      = (const float*)d_in[11];
    const float* mproj_w   = (const float*)d_in[12];
    const float* mproj_b   = (const float*)d_in[13];
    const float* pose_fc_w = (const float*)d_in[14];
    const float* pose_fc_b = (const float*)d_in[15];
    const float* pose_pw   = (const float*)d_in[16];
    const float* pose_pb   = (const float*)d_in[17];
    float* out = (float*)d_out;

    float *a, *qkv, *attmp, *xa, *hbuf, *ph;
    cudaGetSymbolAddress((void**)&a,     g_a);
    cudaGetSymbolAddress((void**)&qkv,   g_qkv);
    cudaGetSymbolAddress((void**)&attmp, g_attm);
    cudaGetSymbolAddress((void**)&xa,    g_xa);
    cudaGetSymbolAddress((void**)&hbuf,  g_h);
    cudaGetSymbolAddress((void**)&ph,    g_ph);

    const size_t OFF = (size_t)S_TOK * DM;
    cudaFuncSetAttribute(attn_kernel, cudaFuncAttributeMaxDynamicSharedMemorySize,
                         ATT_SMEM_BYTES);

    ln_kernel<<<S_TOK, 256>>>(x0, ln1_g, ln1_b, a);
    ln_kernel<<<S_TOK, 256>>>(x1, ln1_g, ln1_b, a + OFF);
    // QKV
    gemm_big_kernel<<<dim3(QKV_N / GBN, S2 / GBM), 128>>>(
        a, attn_w, attn_b, nullptr, qkv, S2, QKV_N, DM, 0);
    attn_kernel<<<dim3(NB, NH, 4), 256, ATT_SMEM_BYTES>>>(
        qkv, qkv + (size_t)S_TOK * QKV_N, attmp, attmp + OFF);
    // attn out projection + residual
    gemm_big_kernel<<<dim3(DM / GBN, S_TOK / GBM), 128>>>(
        attmp, proj_w, proj_b, x0, xa, S_TOK, DM, DM, 0);
    gemm_big_kernel<<<dim3(DM / GBN, S_TOK / GBM), 128>>>(
        attmp + OFF, proj_w, proj_b, x1, xa + OFF, S_TOK, DM, DM, 0);
    ln_kernel<<<S2, 256>>>(xa, ln2_g, ln2_b, a);
    // MLP
    gemm_big_kernel<<<dim3(DI / GBN, S2 / GBM), 128>>>(
        a, fc_w, fc_b, nullptr, hbuf, S2, DI, DM, 1);
    gemm_big_kernel<<<dim3(DM / GBN, S2 / GBM), 128>>>(
        hbuf, mproj_w, mproj_b, xa, out, S2, DM, DI, 0);
    // pose head
    gemm_big_kernel<<<dim3((2 * DM) / GBN, S_TOK / GBM), 128>>>(
        out + OFF, pose_fc_w, pose_fc_b, nullptr, ph, S_TOK, 2 * DM, DM, 1);
    pose_kernel<<<S_TOK, 256>>>(ph, pose_pw, pose_pb, out + 2 * OFF);
}

// round 16
// speedup vs baseline: 2.7626x; 1.5287x over previous
#include <cuda_runtime.h>
#include <cuda_fp16.h>
#include <math.h>
#include <stdint.h>

#define NB    20
#define BSZ   64
#define DM    768
#define NH    12
#define DI    3072
#define QKV_N (3*DM)          // 2304
#define S_TOK (2*NB*BSZ)      // 2560 tokens per stream
#define S2    (2*S_TOK)       // 5120 both streams

// ---------------- scratch (device globals; no allocation allowed) ----------
__device__ float g_a   [S2 * DM];
__device__ float g_qkv [S2 * QKV_N];
__device__ float g_attm[S2 * DM];
__device__ float g_xa  [S2 * DM];
__device__ float g_h   [S2 * DI];
__device__ float g_ph  [S_TOK * 2*DM];

// ---------------- tf32 helpers (attention) ---------------------------------
__device__ __forceinline__ unsigned f2tf32(float f) {
    unsigned u;
    asm("cvt.rna.tf32.f32 %0, %1;" : "=r"(u) : "f"(f));
    return u;
}
__device__ __forceinline__ void tf32split(float x, float& hi, float& lo) {
    unsigned h = f2tf32(x);
    hi = __uint_as_float(h);
    lo = __uint_as_float(f2tf32(x - hi));
}
__device__ __forceinline__ void tf32split_u(float x, unsigned& hi, unsigned& lo) {
    hi = f2tf32(x);
    lo = f2tf32(x - __uint_as_float(hi));
}

#define MMA_TF32(C, Ar, Br) \
    asm volatile( \
        "mma.sync.aligned.m16n8k8.row.col.f32.tf32.tf32.f32 " \
        "{%0,%1,%2,%3}, {%4,%5,%6,%7}, {%8,%9}, {%0,%1,%2,%3};" \
        : "+f"(C[0]), "+f"(C[1]), "+f"(C[2]), "+f"(C[3]) \
        : "r"(Ar[0]), "r"(Ar[1]), "r"(Ar[2]), "r"(Ar[3]), \
          "r"(Br[0]), "r"(Br[1]))

#define MMA_F16(C, Ar, Br) \
    asm volatile( \
        "mma.sync.aligned.m16n8k16.row.col.f32.f16.f16.f32 " \
        "{%0,%1,%2,%3}, {%4,%5,%6,%7}, {%8,%9}, {%0,%1,%2,%3};" \
        : "+f"(C[0]), "+f"(C[1]), "+f"(C[2]), "+f"(C[3]) \
        : "r"(Ar[0]), "r"(Ar[1]), "r"(Ar[2]), "r"(Ar[3]), \
          "r"(Br[0]), "r"(Br[1]))

// fp16 hi/lo split of fp32 (hi 11-bit mantissa; lo captures residual; drop lo*lo ~2^-22)
__device__ __forceinline__ void f16split2(float x, float y, unsigned& hi2, unsigned& lo2) {
    __half hx = __float2half_rn(x), hy = __float2half_rn(y);
    float rx = x - __half2float(hx), ry = y - __half2float(hy);
    __half2 h = __halves2half2(hx, hy);
    __half2 l = __halves2half2(__float2half_rn(rx), __float2half_rn(ry));
    hi2 = *(unsigned*)&h;
    lo2 = *(unsigned*)&l;
}

// ---------------- LayerNorm ------------------------------------------------
__global__ void ln_kernel(const float* __restrict__ x, const float* __restrict__ g,
                          const float* __restrict__ b, float* __restrict__ out) {
    int row = blockIdx.x;
    const float* xr = x + (size_t)row * DM;
    float* orow = out + (size_t)row * DM;
    int t = threadIdx.x;
    float v0 = xr[t], v1 = xr[t + 256], v2 = xr[t + 512];
    float s = v0 + v1 + v2;
    float ss = v0*v0 + v1*v1 + v2*v2;
    #pragma unroll
    for (int o = 16; o; o >>= 1) {
        s  += __shfl_xor_sync(0xffffffffu, s,  o);
        ss += __shfl_xor_sync(0xffffffffu, ss, o);
    }
    __shared__ float rs[8], rss[8];
    __shared__ float mean_s, rstd_s;
    int w = t >> 5;
    if ((t & 31) == 0) { rs[w] = s; rss[w] = ss; }
    __syncthreads();
    if (t == 0) {
        float S = 0.f, SS = 0.f;
        #pragma unroll
        for (int i = 0; i < 8; i++) { S += rs[i]; SS += rss[i]; }
        float m = S * (1.0f / 768.0f);
        float var = SS * (1.0f / 768.0f) - m * m;
        mean_s = m;
        rstd_s = rsqrtf(var + 1e-5f);
    }
    __syncthreads();
    float m = mean_s, r = rstd_s;
    orow[t]       = (v0 - m) * r * g[t]       + b[t];
    orow[t + 256] = (v1 - m) * r * g[t + 256] + b[t + 256];
    orow[t + 512] = (v2 - m) * r * g[t + 512] + b[t + 512];
}

// ============ BIG-TILE 3xFP16 GEMM: CTA 128x128, 4 warps, warp 64x64 =======
// Split to f16 hi/lo at STS time; mainloop = LDS + m16n8k16 MMAs only.
// A smem: [row][k2] h2, row stride 12 words (g*12+tig spans 32 banks).
// B smem: [kp][n] h2 (k-pair packed), row stride 136 words (tig*8+g distinct).
// Per K=16 chunk: 3 MMAs per (mb,nb): lo*hi, hi*lo, hi*hi (term-major).
#define GBM 128
#define GBN 128
#define GBK 16
#define FAS 12                 // A stride in h2 words
#define FBS 136                // B stride in h2 words
#define FASZ (GBM * FAS)       // 1536 words
#define FBSZ (8 * FBS)         // 1088 words

__global__ void __launch_bounds__(128, 2)
gemm_big_kernel(const float* __restrict__ A, const float* __restrict__ B,
                const float* __restrict__ bias, const float* __restrict__ resid,
                float* __restrict__ C, int M, int N, int K, int act) {
    __shared__ unsigned Ah[2][FASZ], Al[2][FASZ];
    __shared__ unsigned Bh[2][FBSZ], Bl[2][FBSZ];

    const int t = threadIdx.x;
    const int warp = t >> 5, lane = t & 31;
    const int g = lane >> 2, tig = lane & 3;
    const int wm = warp >> 1, wn = warp & 1;          // 2x2 warp grid
    const int m0 = blockIdx.y * GBM, n0 = blockIdx.x * GBN;

    // A loader: thread -> rows arow+32q (q=0..3), halfs k = akq*4..+3 (2 h2)
    const int arow = t >> 2, akq = t & 3;
    // B loader: thread -> kp = (t>>5)+4q (q=0..1), n4 = (t&31)*4
    const int bkp = t >> 5, bn4 = (t & 31) * 4;

    float c[4][8][4];
    #pragma unroll
    for (int mb = 0; mb < 4; mb++)
        #pragma unroll
        for (int nb = 0; nb < 8; nb++)
            #pragma unroll
            for (int r = 0; r < 4; r++) c[mb][nb][r] = 0.f;

    const int nIter = K / GBK;

    float4 ra[4], rba[2], rbb[2];
    #pragma unroll
    for (int q = 0; q < 4; q++)
        ra[q] = *(const float4*)&A[(size_t)(m0 + arow + q * 32) * K + akq * 4];
    #pragma unroll
    for (int q = 0; q < 2; q++) {
        int kp = bkp + 4 * q;
        rba[q] = *(const float4*)&B[(size_t)(2 * kp)     * N + n0 + bn4];
        rbb[q] = *(const float4*)&B[(size_t)(2 * kp + 1) * N + n0 + bn4];
    }
    // stage chunk 0
    {
        #pragma unroll
        for (int q = 0; q < 4; q++) {
            int base = (arow + q * 32) * FAS + akq * 2;
            unsigned h0, l0, h1, l1;
            f16split2(ra[q].x, ra[q].y, h0, l0);
            f16split2(ra[q].z, ra[q].w, h1, l1);
            *(uint2*)&Ah[0][base] = make_uint2(h0, h1);
            *(uint2*)&Al[0][base] = make_uint2(l0, l1);
        }
        #pragma unroll
        for (int q = 0; q < 2; q++) {
            int kp = bkp + 4 * q;
            const float* pa = &rba[q].x; const float* pb = &rbb[q].x;
            unsigned h[4], l[4];
            #pragma unroll
            for (int e = 0; e < 4; e++) f16split2(pa[e], pb[e], h[e], l[e]);
            int base = kp * FBS + bn4;
            *(uint4*)&Bh[0][base] = make_uint4(h[0], h[1], h[2], h[3]);
            *(uint4*)&Bl[0][base] = make_uint4(l[0], l[1], l[2], l[3]);
        }
    }
    __syncthreads();

    for (int it = 0; it < nIter; ++it) {
        const int buf = it & 1;
        if (it + 1 < nIter) {
            int k0 = (it + 1) * GBK;
            #pragma unroll
            for (int q = 0; q < 4; q++)
                ra[q] = *(const float4*)&A[(size_t)(m0 + arow + q * 32) * K + k0 + akq * 4];
            #pragma unroll
            for (int q = 0; q < 2; q++) {
                int kp = bkp + 4 * q;
                rba[q] = *(const float4*)&B[(size_t)(k0 + 2 * kp)     * N + n0 + bn4];
                rbb[q] = *(const float4*)&B[(size_t)(k0 + 2 * kp + 1) * N + n0 + bn4];
            }
        }
        const unsigned* ah_s = Ah[buf]; const unsigned* al_s = Al[buf];
        const unsigned* bh_s = Bh[buf]; const unsigned* bl_s = Bl[buf];
        {
            unsigned ah[4][4], al[4][4];
            #pragma unroll
            for (int mb = 0; mb < 4; mb++) {
                int r0 = (wm * 64 + mb * 16 + g) * FAS;
                int r1 = r0 + 8 * FAS;
                ah[mb][0] = ah_s[r0 + tig];     ah[mb][1] = ah_s[r1 + tig];
                ah[mb][2] = ah_s[r0 + tig + 4]; ah[mb][3] = ah_s[r1 + tig + 4];
                al[mb][0] = al_s[r0 + tig];     al[mb][1] = al_s[r1 + tig];
                al[mb][2] = al_s[r0 + tig + 4]; al[mb][3] = al_s[r1 + tig + 4];
            }
            #pragma unroll
            for (int nb = 0; nb < 8; nb++) {
                int col = wn * 64 + nb * 8 + g;
                unsigned bh[2], bl[2];
                bh[0] = bh_s[tig * FBS + col]; bh[1] = bh_s[(tig + 4) * FBS + col];
                bl[0] = bl_s[tig * FBS + col]; bl[1] = bl_s[(tig + 4) * FBS + col];
                #pragma unroll
                for (int mb = 0; mb < 4; mb++) MMA_F16(c[mb][nb], al[mb], bh);
                #pragma unroll
                for (int mb = 0; mb < 4; mb++) MMA_F16(c[mb][nb], ah[mb], bl);
                #pragma unroll
                for (int mb = 0; mb < 4; mb++) MMA_F16(c[mb][nb], ah[mb], bh);
            }
        }
        if (it + 1 < nIter) {
            const int b2 = buf ^ 1;
            #pragma unroll
            for (int q = 0; q < 4; q++) {
                int base = (arow + q * 32) * FAS + akq * 2;
                unsigned h0, l0, h1, l1;
                f16split2(ra[q].x, ra[q].y, h0, l0);
                f16split2(ra[q].z, ra[q].w, h1, l1);
                *(uint2*)&Ah[b2][base] = make_uint2(h0, h1);
                *(uint2*)&Al[b2][base] = make_uint2(l0, l1);
            }
            #pragma unroll
            for (int q = 0; q < 2; q++) {
                int kp = bkp + 4 * q;
                const float* pa = &rba[q].x; const float* pb = &rbb[q].x;
                unsigned h[4], l[4];
                #pragma unroll
                for (int e = 0; e < 4; e++) f16split2(pa[e], pb[e], h[e], l[e]);
                int base = kp * FBS + bn4;
                *(uint4*)&Bh[b2][base] = make_uint4(h[0], h[1], h[2], h[3]);
                *(uint4*)&Bl[b2][base] = make_uint4(l[0], l[1], l[2], l[3]);
            }
        }
        __syncthreads();
    }

    // epilogue
    #pragma unroll
    for (int mb = 0; mb < 4; mb++) {
        int r0 = m0 + wm * 64 + mb * 16 + g;
        #pragma unroll
        for (int nb = 0; nb < 8; nb++) {
            int col = n0 + wn * 64 + nb * 8 + tig * 2;
            float b0 = bias[col], b1 = bias[col + 1];
            #pragma unroll
            for (int half = 0; half < 2; half++) {
                int row = r0 + half * 8;
                float v0 = c[mb][nb][half * 2 + 0] + b0;
                float v1 = c[mb][nb][half * 2 + 1] + b1;
                if (act == 1) {
                    v0 = 0.5f * v0 * (1.0f + erff(v0 * 0.70710678118654752440f));
                    v1 = 0.5f * v1 * (1.0f + erff(v1 * 0.70710678118654752440f));
                }
                if (resid) {
                    const float2 rr = *(const float2*)&resid[(size_t)row * N + col];
                    v0 += rr.x; v1 += rr.y;
                }
                float2 o; o.x = v0; o.y = v1;
                *(float2*)&C[(size_t)row * N + col] = o;
            }
        }
    }
}

// ---------------- Multiend block attention (tensor-core, 3xTF32) -----------
#define AQH 0
#define AQL 4352
#define AKVH 8704
#define AKVL 13312
#define ASS 17920
#define ASTATS 22272
#define ATT_SMEM_FLOATS (ASTATS + 192)
#define ATT_SMEM_BYTES (ATT_SMEM_FLOATS * 4)   // 89856

__global__ void __launch_bounds__(256)
attn_kernel(const float* __restrict__ qkv0, const float* __restrict__ qkv1,
            float* __restrict__ attm0, float* __restrict__ attm1) {
    extern __shared__ float sm[];
    float* q_hi  = sm + AQH;
    float* q_lo  = sm + AQL;
    float* kv_hi = sm + AKVH;
    float* kv_lo = sm + AKVL;
    float* s_s   = sm + ASS;
    float* m_s   = sm + ASTATS;
    float* l_s   = m_s + 64;
    float* al_s  = l_s + 64;

    const int i = blockIdx.x, h = blockIdx.y;
    const int e = blockIdx.z >> 1, b = blockIdx.z & 1;
    const float* qkvE = e ? qkv1 : qkv0;
    float* attm = e ? attm1 : attm0;
    const int t = threadIdx.x;
    const int warp = t >> 5, lane = t & 31;
    const int g = lane >> 2, tig = lane & 3;
    const int wm = warp & 3, wn = warp >> 2;
    const int qrow0 = (b * NB + i) * BSZ;
    const int ar = wm * 16;
    const int nb0 = wn * 32;

    for (int idx = t; idx < 4096; idx += 256) {
        int qi = idx >> 6, d = idx & 63;
        float v = qkvE[(size_t)(qrow0 + qi) * QKV_N + DM + h * 64 + d] * 0.125f;
        float hi, lo;
        tf32split(v, hi, lo);
        q_hi[qi * 68 + d] = hi; q_lo[qi * 68 + d] = lo;
    }
    if (t < 64) { m_s[t] = -1e30f; l_s[t] = 0.f; }
    float acc[4][4] = {};

    for (int j = 0; j <= i; ++j) {
        const float* kvb = (j < i) ? qkv0 : qkvE;
        const int krow0 = (b * NB + j) * BSZ;
        __syncthreads();
        for (int idx = t; idx < 4096; idx += 256) {
            int kj = idx >> 6, d = idx & 63;
            float v = kvb[(size_t)(krow0 + kj) * QKV_N + 2 * DM + h * 64 + d];
            float hi, lo;
            tf32split(v, hi, lo);
            kv_hi[kj * 68 + d] = hi; kv_lo[kj * 68 + d] = lo;
        }
        __syncthreads();
        float sv[4][4] = {};
        #pragma unroll
        for (int ks = 0; ks < 8; ks++) {
            const int kb = ks * 8;
            unsigned ah[4], al[4];
            int i0 = (ar + g) * 68 + kb + tig;
            int i1 = (ar + g + 8) * 68 + kb + tig;
            ah[0] = __float_as_uint(q_hi[i0]);     ah[1] = __float_as_uint(q_hi[i1]);
            ah[2] = __float_as_uint(q_hi[i0 + 4]); ah[3] = __float_as_uint(q_hi[i1 + 4]);
            al[0] = __float_as_uint(q_lo[i0]);     al[1] = __float_as_uint(q_lo[i1]);
            al[2] = __float_as_uint(q_lo[i0 + 4]); al[3] = __float_as_uint(q_lo[i1 + 4]);
            unsigned bh[4][2], bl[4][2];
            #pragma unroll
            for (int jt = 0; jt < 4; jt++) {
                int j0 = (nb0 + jt * 8 + g) * 68 + kb + tig;
                bh[jt][0] = __float_as_uint(kv_hi[j0]); bh[jt][1] = __float_as_uint(kv_hi[j0 + 4]);
                bl[jt][0] = __float_as_uint(kv_lo[j0]); bl[jt][1] = __float_as_uint(kv_lo[j0 + 4]);
            }
            #pragma unroll
            for (int jt = 0; jt < 4; jt++) MMA_TF32(sv[jt], al, bh[jt]);
            #pragma unroll
            for (int jt = 0; jt < 4; jt++) MMA_TF32(sv[jt], ah, bl[jt]);
            #pragma unroll
            for (int jt = 0; jt < 4; jt++) MMA_TF32(sv[jt], ah, bh[jt]);
        }
        #pragma unroll
        for (int jt = 0; jt < 4; jt++) {
            int col = nb0 + jt * 8 + 2 * tig;
            float2 v01; v01.x = sv[jt][0]; v01.y = sv[jt][1];
            float2 v23; v23.x = sv[jt][2]; v23.y = sv[jt][3];
            *(float2*)&s_s[(ar + g) * 68 + col]     = v01;
            *(float2*)&s_s[(ar + g + 8) * 68 + col] = v23;
        }
        __syncthreads();
        {
            int q = t >> 2, p = t & 3;
            int base = q * 68 + p * 16;
            float lm = -1e30f;
            #pragma unroll
            for (int kk = 0; kk < 16; kk++) lm = fmaxf(lm, s_s[base + kk]);
            lm = fmaxf(lm, __shfl_xor_sync(0xffffffffu, lm, 1));
            lm = fmaxf(lm, __shfl_xor_sync(0xffffffffu, lm, 2));
            float mold = m_s[q];
            float mnew = fmaxf(mold, lm);
            float ls = 0.f;
            #pragma unroll
            for (int kk = 0; kk < 16; kk++) {
                float pp = __expf(s_s[base + kk] - mnew);
                s_s[base + kk] = pp;
                ls += pp;
            }
            ls += __shfl_xor_sync(0xffffffffu, ls, 1);
            ls += __shfl_xor_sync(0xffffffffu, ls, 2);
            if (p == 0) {
                float alpha = __expf(mold - mnew);
                al_s[q] = alpha;
                l_s[q] = l_s[q] * alpha + ls;
                m_s[q] = mnew;
            }
        }
        for (int idx = t; idx < 4096; idx += 256) {
            int kj = idx >> 6, d = idx & 63;
            float v = kvb[(size_t)(krow0 + kj) * QKV_N + h * 64 + d];
            float hi, lo;
            tf32split(v, hi, lo);
            kv_hi[kj * 72 + d] = hi; kv_lo[kj * 72 + d] = lo;
        }
        __syncthreads();
        {
            float a0 = al_s[ar + g], a1 = al_s[ar + g + 8];
            #pragma unroll
            for (int jt = 0; jt < 4; jt++) {
                acc[jt][0] *= a0; acc[jt][1] *= a0;
                acc[jt][2] *= a1; acc[jt][3] *= a1;
            }
        }
        #pragma unroll
        for (int ks = 0; ks < 8; ks++) {
            const int kb = ks * 8;
            int i0 = (ar + g) * 68 + kb + tig;
            int i1 = (ar + g + 8) * 68 + kb + tig;
            unsigned ah[4], al[4];
            tf32split_u(s_s[i0],     ah[0], al[0]);
            tf32split_u(s_s[i1],     ah[1], al[1]);
            tf32split_u(s_s[i0 + 4], ah[2], al[2]);
            tf32split_u(s_s[i1 + 4], ah[3], al[3]);
            unsigned bh[4][2], bl[4][2];
            #pragma unroll
            for (int jt = 0; jt < 4; jt++) {
                int nb = nb0 + jt * 8;
                int j0 = (kb + tig) * 72 + nb + g;
                int j1 = (kb + tig + 4) * 72 + nb + g;
                bh[jt][0] = __float_as_uint(kv_hi[j0]); bh[jt][1] = __float_as_uint(kv_hi[j1]);
                bl[jt][0] = __float_as_uint(kv_lo[j0]); bl[jt][1] = __float_as_uint(kv_lo[j1]);
            }
            #pragma unroll
            for (int jt = 0; jt < 4; jt++) MMA_TF32(acc[jt], al, bh[jt]);
            #pragma unroll
            for (int jt = 0; jt < 4; jt++) MMA_TF32(acc[jt], ah, bl[jt]);
            #pragma unroll
            for (int jt = 0; jt < 4; jt++) MMA_TF32(acc[jt], ah, bh[jt]);
        }
    }
    {
        const int r0 = ar + g, r1 = ar + g + 8;
        const float inv0 = 1.0f / l_s[r0], inv1 = 1.0f / l_s[r1];
        #pragma unroll
        for (int jt = 0; jt < 4; jt++) {
            int col = h * 64 + nb0 + jt * 8 + 2 * tig;
            float2 o0; o0.x = acc[jt][0] * inv0; o0.y = acc[jt][1] * inv0;
            float2 o1; o1.x = acc[jt][2] * inv1; o1.y = acc[jt][3] * inv1;
            *(float2*)&attm[(size_t)(qrow0 + r0) * DM + col] = o0;
            *(float2*)&attm[(size_t)(qrow0 + r1) * DM + col] = o1;
        }
    }
}

// ---------------- Pose projection + quaternion normalize -------------------
__global__ void pose_kernel(const float* __restrict__ ph, const float* __restrict__ w,
                            const float* __restrict__ bias, float* __restrict__ out) {
    int row = blockIdx.x;
    int t = threadIdx.x;
    const float* hr = ph + (size_t)row * (2 * DM);
    float part[7] = {};
    for (int j = t; j < 2 * DM; j += 256) {
        float hv = hr[j];
        #pragma unroll
        for (int o = 0; o < 7; o++) part[o] += hv * w[j * 7 + o];
    }
    #pragma unroll
    for (int o = 0; o < 7; o++)
        #pragma unroll
        for (int s = 16; s; s >>= 1)
            part[o] += __shfl_xor_sync(0xffffffffu, part[o], s);
    __shared__ float red[8][7];
    int wi = t >> 5;
    if ((t & 31) == 0)
        #pragma unroll
        for (int o = 0; o < 7; o++) red[wi][o] = part[o];
    __syncthreads();
    if (t == 0) {
        float hv[7];
        #pragma unroll
        for (int o = 0; o < 7; o++) {
            hv[o] = bias[o];
            for (int k = 0; k < 8; k++) hv[o] += red[k][o];
        }
        float q0 = hv[3], q1 = hv[4], q2 = hv[5], q3 = hv[6];
        float inv = rsqrtf(q0*q0 + q1*q1 + q2*q2 + q3*q3);
        q0 *= inv; q1 *= inv; q2 *= inv; q3 *= inv;
        if (q0 < 0.f) { q0 = -q0; q1 = -q1; q2 = -q2; q3 = -q3; }
        float* orow = out + (size_t)row * 7;
        orow[0] = hv[0]; orow[1] = hv[1]; orow[2] = hv[2];
        orow[3] = q0; orow[4] = q1; orow[5] = q2; orow[6] = q3;
    }
}

// ---------------------------------------------------------------------------
extern "C" void kernel_launch(void* const* d_in, const int* in_sizes, int n_in,
                              void* d_out, int out_size) {
    const float* x0        = (const float*)d_in[0];
    const float* x1        = (const float*)d_in[1];
    const float* ln1_g     = (const float*)d_in[2];
    const float* ln1_b     = (const float*)d_in[3];
    const float* attn_w    = (const float*)d_in[4];
    const float* attn_b    = (const float*)d_in[5];
    const float* proj_w    = (const float*)d_in[6];
    const float* proj_b    = (const float*)d_in[7];
    const float* ln2_g     = (const float*)d_in[8];
    const float* ln2_b     = (const float*)d_in[9];
    const float* fc_w      = (const float*)d_in[10];
    const float* fc_b      = (const float*)d_in[11];
    const float* mproj_w   = (const float*)d_in[12];
    const float* mproj_b   = (const float*)d_in[13];
    const float* pose_fc_w = (const float*)d_in[14];
    const float* pose_fc_b = (const float*)d_in[15];
    const float* pose_pw   = (const float*)d_in[16];
    const float* pose_pb   = (const float*)d_in[17];
    float* out = (float*)d_out;

    float *a, *qkv, *attmp, *xa, *hbuf, *ph;
    cudaGetSymbolAddress((void**)&a,     g_a);
    cudaGetSymbolAddress((void**)&qkv,   g_qkv);
    cudaGetSymbolAddress((void**)&attmp, g_attm);
    cudaGetSymbolAddress((void**)&xa,    g_xa);
    cudaGetSymbolAddress((void**)&hbuf,  g_h);
    cudaGetSymbolAddress((void**)&ph,    g_ph);

    const size_t OFF = (size_t)S_TOK * DM;
    cudaFuncSetAttribute(attn_kernel, cudaFuncAttributeMaxDynamicSharedMemorySize,
                         ATT_SMEM_BYTES);

    ln_kernel<<<S_TOK, 256>>>(x0, ln1_g, ln1_b, a);
    ln_kernel<<<S_TOK, 256>>>(x1, ln1_g, ln1_b, a + OFF);
    // QKV
    gemm_big_kernel<<<dim3(QKV_N / GBN, S2 / GBM), 128>>>(
        a, attn_w, attn_b, nullptr, qkv, S2, QKV_N, DM, 0);
    attn_kernel<<<dim3(NB, NH, 4), 256, ATT_SMEM_BYTES>>>(
        qkv, qkv + (size_t)S_TOK * QKV_N, attmp, attmp + OFF);
    // attn out projection + residual
    gemm_big_kernel<<<dim3(DM / GBN, S_TOK / GBM), 128>>>(
        attmp, proj_w, proj_b, x0, xa, S_TOK, DM, DM, 0);
    gemm_big_kernel<<<dim3(DM / GBN, S_TOK / GBM), 128>>>(
        attmp + OFF, proj_w, proj_b, x1, xa + OFF, S_TOK, DM, DM, 0);
    ln_kernel<<<S2, 256>>>(xa, ln2_g, ln2_b, a);
    // MLP
    gemm_big_kernel<<<dim3(DI / GBN, S2 / GBM), 128>>>(
        a, fc_w, fc_b, nullptr, hbuf, S2, DI, DM, 1);
    gemm_big_kernel<<<dim3(DM / GBN, S2 / GBM), 128>>>(
        hbuf, mproj_w, mproj_b, xa, out, S2, DM, DI, 0);
    // pose head
    gemm_big_kernel<<<dim3((2 * DM) / GBN, S_TOK / GBM), 128>>>(
        out + OFF, pose_fc_w, pose_fc_b, nullptr, ph, S_TOK, 2 * DM, DM, 1);
    pose_kernel<<<S_TOK, 256>>>(ph, pose_pw, pose_pb, out + 2 * OFF);
}